// round 1
// baseline (speedup 1.0000x reference)
#include <cuda_runtime.h>
#include <cuda_bf16.h>
#include <cstdint>
#include <math.h>

// ---------------------------------------------------------------------------
// TransformerBlock: B=2, C=384, N=2048 tokens/batch (8*16*16), H=8 heads, d=48
// MLP hidden 1536, exact-erf GELU, LN eps 1e-6, fp32 everywhere.
// ---------------------------------------------------------------------------

#define BATCH   2
#define DIM     384
#define NTOK    2048            // tokens per batch
#define MTOT    (BATCH * NTOK)  // 4096 rows total
#define NHEADS  8
#define HDIM    48
#define QKVC    (3 * DIM)       // 1152
#define MLPH    1536
#define ATT_SCALE 0.14433756729740643f   // 48^-0.5

// ----------------------------- scratch ------------------------------------
__device__ float g_h  [MTOT * DIM];    // residual stream
__device__ float g_hn [MTOT * DIM];    // normalized
__device__ float g_qkv[MTOT * QKVC];
__device__ float g_att[MTOT * DIM];
__device__ float g_mlp[MTOT * MLPH];

// ------------------------ kernel 1: transpose + LN1 ------------------------
// x: [B, C, N] -> h: [B, N, C] (copy) and hn = LN(h)
#define TT 16
__global__ void k_transpose_ln(const float* __restrict__ x,
                               const float* __restrict__ g,
                               const float* __restrict__ b,
                               float* __restrict__ h,
                               float* __restrict__ hn)
{
    __shared__ float tile[TT][DIM + 1];
    const int tilesPerBatch = NTOK / TT;           // 128
    const int bb = blockIdx.x / tilesPerBatch;
    const int n0 = (blockIdx.x % tilesPerBatch) * TT;
    const float* xb = x + (size_t)bb * DIM * NTOK;

    for (int idx = threadIdx.x; idx < DIM * TT; idx += blockDim.x) {
        int c = idx / TT, t = idx % TT;
        tile[t][c] = xb[(size_t)c * NTOK + n0 + t];
    }
    __syncthreads();

    const int wid = threadIdx.x >> 5, lane = threadIdx.x & 31;
    for (int t = wid; t < TT; t += (int)(blockDim.x >> 5)) {
        float s = 0.f;
        #pragma unroll
        for (int c = lane; c < DIM; c += 32) s += tile[t][c];
        #pragma unroll
        for (int o = 16; o; o >>= 1) s += __shfl_xor_sync(0xffffffffu, s, o);
        float mu = s * (1.f / DIM);
        float vs = 0.f;
        #pragma unroll
        for (int c = lane; c < DIM; c += 32) { float d = tile[t][c] - mu; vs += d * d; }
        #pragma unroll
        for (int o = 16; o; o >>= 1) vs += __shfl_xor_sync(0xffffffffu, vs, o);
        float rstd = rsqrtf(vs * (1.f / DIM) + 1e-6f);
        size_t row = ((size_t)bb * NTOK + n0 + t) * DIM;
        for (int c = lane; c < DIM; c += 32) {
            float v = tile[t][c];
            h[row + c]  = v;
            hn[row + c] = (v - mu) * rstd * g[c] + b[c];
        }
    }
}

// -------------------------- kernel 2: SGEMM -------------------------------
// C[M,N] = A[M,K] @ B[K,N] (+bias) (+GELU) (+res)
template<bool BIAS, bool GELU, bool RES>
__global__ void __launch_bounds__(256)
k_sgemm(const float* __restrict__ A, const float* __restrict__ B,
        const float* __restrict__ bias, const float* __restrict__ res,
        float* __restrict__ C, int M, int N, int K)
{
    constexpr int BM = 128, BN = 128, BK = 8;
    __shared__ float As[BK][BM];
    __shared__ float Bs[BK][BN];

    const int tid = threadIdx.x;
    const int m0 = blockIdx.y * BM;
    const int n0 = blockIdx.x * BN;
    const int tx = tid & 15;       // col group
    const int ty = tid >> 4;       // row group

    float acc[8][8];
    #pragma unroll
    for (int i = 0; i < 8; i++)
        #pragma unroll
        for (int j = 0; j < 8; j++) acc[i][j] = 0.f;

    const int arow = tid >> 1;
    const int acol = (tid & 1) * 4;
    const int brow = tid >> 5;
    const int bcol = (tid & 31) * 4;
    const float* Aptr = A + (size_t)(m0 + arow) * K + acol;
    const float* Bptr = B + (size_t)brow * N + n0 + bcol;

    for (int k0 = 0; k0 < K; k0 += BK) {
        float4 a4 = *(const float4*)(Aptr + k0);
        float4 b4 = *(const float4*)(Bptr + (size_t)k0 * N);
        As[acol + 0][arow] = a4.x;
        As[acol + 1][arow] = a4.y;
        As[acol + 2][arow] = a4.z;
        As[acol + 3][arow] = a4.w;
        *(float4*)&Bs[brow][bcol] = b4;
        __syncthreads();
        #pragma unroll
        for (int k = 0; k < BK; k++) {
            float ar[8], br[8];
            #pragma unroll
            for (int i = 0; i < 8; i++) ar[i] = As[k][ty * 8 + i];
            #pragma unroll
            for (int j = 0; j < 8; j++) br[j] = Bs[k][tx * 8 + j];
            #pragma unroll
            for (int i = 0; i < 8; i++)
                #pragma unroll
                for (int j = 0; j < 8; j++) acc[i][j] += ar[i] * br[j];
        }
        __syncthreads();
    }

    #pragma unroll
    for (int i = 0; i < 8; i++) {
        size_t m = (size_t)m0 + ty * 8 + i;
        #pragma unroll
        for (int j = 0; j < 8; j++) {
            int n = n0 + tx * 8 + j;
            float v = acc[i][j];
            if (BIAS) v += bias[n];
            if (GELU) v = 0.5f * v * (1.f + erff(v * 0.70710678118654752f));
            if (RES)  v += res[m * N + n];
            C[m * N + n] = v;
        }
    }
}

// --------------------- kernel 3: flash attention (fp32) --------------------
// qkv: [B*N, 1152] where col = qkv_i*384 + head*48 + dd
// attn: [B*N, 384]
__global__ void __launch_bounds__(128)
k_attn(const float* __restrict__ qkv, float* __restrict__ attn)
{
    constexpr int BQ = 32, BK = 64, D = HDIM;
    __shared__ float Qs[BQ * D];          // 1536
    __shared__ float Ks[BK * D];          // 3072
    __shared__ float Vs[BK * D];          // 3072
    __shared__ float Ss[BQ * (BK + 1)];   // 2080
    __shared__ float mS[BQ], lS[BQ], fS[BQ];

    const int bh = blockIdx.y;
    const int bb = bh >> 3, hh = bh & 7;
    const float* base = qkv + (size_t)bb * NTOK * QKVC + hh * HDIM;
    const int q0 = blockIdx.x * BQ;
    const int tid = threadIdx.x;
    const int ty = tid >> 4;   // 0..7  -> 4 rows each
    const int tx = tid & 15;   // 0..15 -> 4 S-cols / 3 O-cols each

    for (int idx = tid; idx < BQ * D; idx += 128) {
        int r = idx / D, c = idx % D;
        Qs[idx] = base[(size_t)(q0 + r) * QKVC + c] * ATT_SCALE;
    }
    if (tid < BQ) { mS[tid] = -3.0e38f; lS[tid] = 0.f; }

    float o[4][3];
    #pragma unroll
    for (int i = 0; i < 4; i++)
        #pragma unroll
        for (int j = 0; j < 3; j++) o[i][j] = 0.f;

    for (int kt = 0; kt < NTOK / BK; kt++) {
        const int k0 = kt * BK;
        __syncthreads();   // previous tile fully consumed
        for (int idx = tid; idx < BK * D; idx += 128) {
            int r = idx / D, c = idx % D;
            size_t rowoff = (size_t)(k0 + r) * QKVC + c;
            Ks[idx] = base[rowoff + DIM];
            Vs[idx] = base[rowoff + 2 * DIM];
        }
        __syncthreads();

        // S tile: rows ty*4.., cols tx*4..
        float acc[4][4];
        #pragma unroll
        for (int i = 0; i < 4; i++)
            #pragma unroll
            for (int j = 0; j < 4; j++) acc[i][j] = 0.f;
        #pragma unroll 4
        for (int kk = 0; kk < D; kk++) {
            float a[4], b[4];
            #pragma unroll
            for (int i = 0; i < 4; i++) a[i] = Qs[(ty * 4 + i) * D + kk];
            #pragma unroll
            for (int j = 0; j < 4; j++) b[j] = Ks[(tx * 4 + j) * D + kk];
            #pragma unroll
            for (int i = 0; i < 4; i++)
                #pragma unroll
                for (int j = 0; j < 4; j++) acc[i][j] += a[i] * b[j];
        }
        #pragma unroll
        for (int i = 0; i < 4; i++)
            #pragma unroll
            for (int j = 0; j < 4; j++)
                Ss[(ty * 4 + i) * (BK + 1) + tx * 4 + j] = acc[i][j];
        __syncthreads();

        // online softmax, one thread per row
        if (tid < BQ) {
            const int r = tid;
            float mprev = mS[r];
            float mx = mprev;
            #pragma unroll 8
            for (int j = 0; j < BK; j++) mx = fmaxf(mx, Ss[r * (BK + 1) + j]);
            float f = expf(mprev - mx);
            float sum = 0.f;
            #pragma unroll 8
            for (int j = 0; j < BK; j++) {
                float p = expf(Ss[r * (BK + 1) + j] - mx);
                Ss[r * (BK + 1) + j] = p;
                sum += p;
            }
            lS[r] = lS[r] * f + sum;
            mS[r] = mx;
            fS[r] = f;
        }
        __syncthreads();

        // rescale O and accumulate P @ V : O rows ty*4.., cols tx*3..
        float fi[4];
        #pragma unroll
        for (int i = 0; i < 4; i++) fi[i] = fS[ty * 4 + i];
        #pragma unroll
        for (int i = 0; i < 4; i++)
            #pragma unroll
            for (int j = 0; j < 3; j++) o[i][j] *= fi[i];
        #pragma unroll 4
        for (int kk = 0; kk < BK; kk++) {
            float p[4], v[3];
            #pragma unroll
            for (int i = 0; i < 4; i++) p[i] = Ss[(ty * 4 + i) * (BK + 1) + kk];
            #pragma unroll
            for (int j = 0; j < 3; j++) v[j] = Vs[kk * D + tx * 3 + j];
            #pragma unroll
            for (int i = 0; i < 4; i++)
                #pragma unroll
                for (int j = 0; j < 3; j++) o[i][j] += p[i] * v[j];
        }
    }

    #pragma unroll
    for (int i = 0; i < 4; i++) {
        float inv = 1.f / lS[ty * 4 + i];
        size_t row = ((size_t)bb * NTOK + q0 + ty * 4 + i) * DIM + hh * HDIM + tx * 3;
        #pragma unroll
        for (int j = 0; j < 3; j++) attn[row + j] = o[i][j] * inv;
    }
}

// --------------------------- kernel 4: LN ---------------------------------
__global__ void k_ln(const float* __restrict__ in, const float* __restrict__ g,
                     const float* __restrict__ b, float* __restrict__ out)
{
    const int row = blockIdx.x;
    const float* p = in + (size_t)row * DIM;
    const int t = threadIdx.x;
    float v0 = p[t], v1 = p[t + 128], v2 = p[t + 256];
    float s = v0 + v1 + v2;

    __shared__ float red[4];
    #pragma unroll
    for (int o = 16; o; o >>= 1) s += __shfl_xor_sync(0xffffffffu, s, o);
    if ((t & 31) == 0) red[t >> 5] = s;
    __syncthreads();
    float mu = (red[0] + red[1] + red[2] + red[3]) * (1.f / DIM);

    float d0 = v0 - mu, d1 = v1 - mu, d2 = v2 - mu;
    float q = d0 * d0 + d1 * d1 + d2 * d2;
    __syncthreads();
    #pragma unroll
    for (int o = 16; o; o >>= 1) q += __shfl_xor_sync(0xffffffffu, q, o);
    if ((t & 31) == 0) red[t >> 5] = q;
    __syncthreads();
    float rstd = rsqrtf((red[0] + red[1] + red[2] + red[3]) * (1.f / DIM) + 1e-6f);

    float* po = out + (size_t)row * DIM;
    po[t]       = d0 * rstd * g[t]       + b[t];
    po[t + 128] = d1 * rstd * g[t + 128] + b[t + 128];
    po[t + 256] = d2 * rstd * g[t + 256] + b[t + 256];
}

// ---------------------- kernel 5: transpose back ---------------------------
// h: [B, N, C] -> out: [B, C, N]
__global__ void k_transpose_out(const float* __restrict__ h, float* __restrict__ out)
{
    __shared__ float tile[TT][DIM + 1];
    const int tilesPerBatch = NTOK / TT;
    const int bb = blockIdx.x / tilesPerBatch;
    const int n0 = (blockIdx.x % tilesPerBatch) * TT;

    for (int idx = threadIdx.x; idx < DIM * TT; idx += blockDim.x) {
        int t = idx / DIM, c = idx % DIM;
        tile[t][c] = h[((size_t)bb * NTOK + n0 + t) * DIM + c];
    }
    __syncthreads();
    float* ob = out + (size_t)bb * DIM * NTOK;
    for (int idx = threadIdx.x; idx < DIM * TT; idx += blockDim.x) {
        int c = idx / TT, t = idx % TT;
        ob[(size_t)c * NTOK + n0 + t] = tile[t][c];
    }
}

// ------------------------------- launch ------------------------------------
extern "C" void kernel_launch(void* const* d_in, const int* in_sizes, int n_in,
                              void* d_out, int out_size)
{
    const float* x    = (const float*)d_in[0];
    const float* g1   = (const float*)d_in[1];
    const float* b1   = (const float*)d_in[2];
    const float* Wqkv = (const float*)d_in[3];
    const float* Wo   = (const float*)d_in[4];
    const float* bo   = (const float*)d_in[5];
    const float* g2   = (const float*)d_in[6];
    const float* b2   = (const float*)d_in[7];
    const float* W1   = (const float*)d_in[8];
    const float* b1m  = (const float*)d_in[9];
    const float* W2   = (const float*)d_in[10];
    const float* b2m  = (const float*)d_in[11];
    float* out = (float*)d_out;

    float *h, *hn, *qkv, *att, *mlp;
    cudaGetSymbolAddress((void**)&h,   g_h);
    cudaGetSymbolAddress((void**)&hn,  g_hn);
    cudaGetSymbolAddress((void**)&qkv, g_qkv);
    cudaGetSymbolAddress((void**)&att, g_att);
    cudaGetSymbolAddress((void**)&mlp, g_mlp);

    // 1. transpose + LN1
    k_transpose_ln<<<MTOT / TT, 256>>>(x, g1, b1, h, hn);
    // 2. QKV = hn @ Wqkv
    k_sgemm<false, false, false><<<dim3(QKVC / 128, MTOT / 128), 256>>>(
        hn, Wqkv, nullptr, nullptr, qkv, MTOT, QKVC, DIM);
    // 3. attention
    k_attn<<<dim3(NTOK / 32, BATCH * NHEADS), 128>>>(qkv, att);
    // 4. h += att @ Wo + bo
    k_sgemm<true, false, true><<<dim3(DIM / 128, MTOT / 128), 256>>>(
        att, Wo, bo, h, h, MTOT, DIM, DIM);
    // 5. LN2
    k_ln<<<MTOT, 128>>>(h, g2, b2, hn);
    // 6. mlp = gelu(hn @ W1 + b1m)
    k_sgemm<true, true, false><<<dim3(MLPH / 128, MTOT / 128), 256>>>(
        hn, W1, b1m, nullptr, mlp, MTOT, MLPH, DIM);
    // 7. h += mlp @ W2 + b2m
    k_sgemm<true, false, true><<<dim3(DIM / 128, MTOT / 128), 256>>>(
        mlp, W2, b2m, h, h, MTOT, DIM, MLPH);
    // 8. transpose back
    k_transpose_out<<<MTOT / TT, 256>>>(h, out);
}

// round 2
// speedup vs baseline: 4.1634x; 4.1634x over previous
#include <cuda_runtime.h>
#include <cuda_bf16.h>
#include <cstdint>
#include <math.h>

// ---------------------------------------------------------------------------
// TransformerBlock: B=2, C=384, N=2048 tokens/batch, H=8 heads, d=48
// MLP hidden 1536, exact-erf GELU, LN eps 1e-6. fp32 I/O, tf32 tensor math.
// ---------------------------------------------------------------------------

#define BATCH   2
#define DIM     384
#define NTOK    2048
#define MTOT    (BATCH * NTOK)  // 4096
#define NHEADS  8
#define HDIM    48
#define QKVC    (3 * DIM)       // 1152
#define MLPH    1536
#define ATT_SCALE 0.14433756729740643f

// ----------------------------- scratch ------------------------------------
__device__ float g_h  [MTOT * DIM];
__device__ float g_hn [MTOT * DIM];
__device__ float g_qkv[MTOT * QKVC];
__device__ float g_att[MTOT * DIM];
__device__ float g_mlp[MTOT * MLPH];

// --------------------------- tf32 helpers ----------------------------------
__device__ __forceinline__ float f2t(float x) {
    uint32_t u;
    asm("cvt.rna.tf32.f32 %0, %1;" : "=r"(u) : "f"(x));
    return __uint_as_float(u);
}

// D += A(16x8,row) * B(8x8,col) ; operands are tf32 bit patterns in floats
__device__ __forceinline__ void mma8(float* c, const float* a, const float* b) {
    asm volatile(
        "mma.sync.aligned.m16n8k8.row.col.f32.tf32.tf32.f32 "
        "{%0,%1,%2,%3}, {%4,%5,%6,%7}, {%8,%9}, {%0,%1,%2,%3};\n"
        : "+f"(c[0]), "+f"(c[1]), "+f"(c[2]), "+f"(c[3])
        : "r"(__float_as_uint(a[0])), "r"(__float_as_uint(a[1])),
          "r"(__float_as_uint(a[2])), "r"(__float_as_uint(a[3])),
          "r"(__float_as_uint(b[0])), "r"(__float_as_uint(b[1])));
}

// ------------------------ kernel 1: transpose + LN1 ------------------------
#define TT 16
__global__ void k_transpose_ln(const float* __restrict__ x,
                               const float* __restrict__ g,
                               const float* __restrict__ b,
                               float* __restrict__ h,
                               float* __restrict__ hn)
{
    __shared__ float tile[TT][DIM + 1];
    const int tilesPerBatch = NTOK / TT;
    const int bb = blockIdx.x / tilesPerBatch;
    const int n0 = (blockIdx.x % tilesPerBatch) * TT;
    const float* xb = x + (size_t)bb * DIM * NTOK;

    for (int idx = threadIdx.x; idx < DIM * TT; idx += blockDim.x) {
        int c = idx / TT, t = idx % TT;
        tile[t][c] = xb[(size_t)c * NTOK + n0 + t];
    }
    __syncthreads();

    const int wid = threadIdx.x >> 5, lane = threadIdx.x & 31;
    for (int t = wid; t < TT; t += (int)(blockDim.x >> 5)) {
        float s = 0.f;
        #pragma unroll
        for (int c = lane; c < DIM; c += 32) s += tile[t][c];
        #pragma unroll
        for (int o = 16; o; o >>= 1) s += __shfl_xor_sync(0xffffffffu, s, o);
        float mu = s * (1.f / DIM);
        float vs = 0.f;
        #pragma unroll
        for (int c = lane; c < DIM; c += 32) { float d = tile[t][c] - mu; vs += d * d; }
        #pragma unroll
        for (int o = 16; o; o >>= 1) vs += __shfl_xor_sync(0xffffffffu, vs, o);
        float rstd = rsqrtf(vs * (1.f / DIM) + 1e-6f);
        size_t row = ((size_t)bb * NTOK + n0 + t) * DIM;
        for (int c = lane; c < DIM; c += 32) {
            float v = tile[t][c];
            h[row + c]  = v;
            hn[row + c] = (v - mu) * rstd * g[c] + b[c];
        }
    }
}

// ----------------- kernel 2: tf32 tensor-core GEMM -------------------------
// C[M,N] = A[M,K] @ B[K,N] (+bias)(+GELU)(+res).  BM=128, BK=16.
// 8 warps: warp_m = wid%4 (32 rows, 2 m-steps), warp_n = wid/4 (BN/2 cols).
template<int BN, bool BIAS, bool GELU, bool RES>
__global__ void __launch_bounds__(256)
k_mmagemm(const float* __restrict__ A, const float* __restrict__ B,
          const float* __restrict__ bias, const float* __restrict__ res,
          float* __restrict__ C, int M, int N, int K)
{
    constexpr int BM = 128, BK = 16;
    constexpr int NS = BN / 16;         // n-steps per warp (8 or 4)
    __shared__ float As[BK * 136];      // As[k][m], stride 136
    __shared__ float Bs[BK * 136];      // Bs[k][n], stride 136

    const int tid = threadIdx.x;
    const int m0 = blockIdx.y * BM;
    const int n0 = blockIdx.x * BN;
    const int wid = tid >> 5, lane = tid & 31;
    const int g  = lane >> 2;           // 0..7
    const int tg = lane & 3;            // 0..3
    const int wm0 = (wid & 3) * 32;
    const int wn0 = (wid >> 2) * (BN / 2);

    float acc[2][NS][4];
    #pragma unroll
    for (int i = 0; i < 2; i++)
        #pragma unroll
        for (int j = 0; j < NS; j++)
            #pragma unroll
            for (int q = 0; q < 4; q++) acc[i][j][q] = 0.f;

    // global-load mapping
    const int a_m = tid >> 1, a_c = (tid & 1) * 8;           // 2 float4 per thread
    constexpr int EB = BN / 16;                               // floats/thread for B (8 or 4)
    const int b_k = tid >> 4;
    const int b_n = (tid & 15) * EB;

    const float* Ap = A + (size_t)(m0 + a_m) * K + a_c;
    const float* Bp = B + (size_t)b_k * N + n0 + b_n;

    float4 ra0 = *(const float4*)(Ap);
    float4 ra1 = *(const float4*)(Ap + 4);
    float4 rb0 = *(const float4*)(Bp);
    float4 rb1 = (EB == 8) ? *(const float4*)(Bp + 4) : make_float4(0, 0, 0, 0);

    for (int k0 = 0; k0 < K; k0 += BK) {
        // store current tile to smem (tf32-rounded)
        As[(a_c + 0) * 136 + a_m] = f2t(ra0.x);
        As[(a_c + 1) * 136 + a_m] = f2t(ra0.y);
        As[(a_c + 2) * 136 + a_m] = f2t(ra0.z);
        As[(a_c + 3) * 136 + a_m] = f2t(ra0.w);
        As[(a_c + 4) * 136 + a_m] = f2t(ra1.x);
        As[(a_c + 5) * 136 + a_m] = f2t(ra1.y);
        As[(a_c + 6) * 136 + a_m] = f2t(ra1.z);
        As[(a_c + 7) * 136 + a_m] = f2t(ra1.w);
        {
            float4 t0 = make_float4(f2t(rb0.x), f2t(rb0.y), f2t(rb0.z), f2t(rb0.w));
            *(float4*)&Bs[b_k * 136 + b_n] = t0;
            if (EB == 8) {
                float4 t1 = make_float4(f2t(rb1.x), f2t(rb1.y), f2t(rb1.z), f2t(rb1.w));
                *(float4*)&Bs[b_k * 136 + b_n + 4] = t1;
            }
        }
        __syncthreads();

        if (k0 + BK < K) {  // prefetch next
            ra0 = *(const float4*)(Ap + k0 + BK);
            ra1 = *(const float4*)(Ap + k0 + BK + 4);
            rb0 = *(const float4*)(Bp + (size_t)(k0 + BK) * N);
            if (EB == 8) rb1 = *(const float4*)(Bp + (size_t)(k0 + BK) * N + 4);
        }

        #pragma unroll
        for (int kk = 0; kk < 2; kk++) {
            const int kb = kk * 8;
            float ar[2][4];
            #pragma unroll
            for (int ms = 0; ms < 2; ms++) {
                int m = wm0 + ms * 16 + g;
                ar[ms][0] = As[(kb + tg) * 136 + m];
                ar[ms][1] = As[(kb + tg) * 136 + m + 8];
                ar[ms][2] = As[(kb + tg + 4) * 136 + m];
                ar[ms][3] = As[(kb + tg + 4) * 136 + m + 8];
            }
            #pragma unroll
            for (int ns = 0; ns < NS; ns++) {
                float br[2];
                int n = wn0 + ns * 8 + g;
                br[0] = Bs[(kb + tg) * 136 + n];
                br[1] = Bs[(kb + tg + 4) * 136 + n];
                #pragma unroll
                for (int ms = 0; ms < 2; ms++) mma8(acc[ms][ns], ar[ms], br);
            }
        }
        __syncthreads();
    }

    // epilogue
    #pragma unroll
    for (int ms = 0; ms < 2; ms++) {
        #pragma unroll
        for (int rr = 0; rr < 2; rr++) {
            size_t m = (size_t)m0 + wm0 + ms * 16 + g + rr * 8;
            #pragma unroll
            for (int ns = 0; ns < NS; ns++) {
                int n = n0 + wn0 + ns * 8 + tg * 2;
                float v0 = acc[ms][ns][rr * 2 + 0];
                float v1 = acc[ms][ns][rr * 2 + 1];
                if (BIAS) { v0 += bias[n]; v1 += bias[n + 1]; }
                if (GELU) {
                    v0 = 0.5f * v0 * (1.f + erff(v0 * 0.70710678118654752f));
                    v1 = 0.5f * v1 * (1.f + erff(v1 * 0.70710678118654752f));
                }
                if (RES) {
                    v0 += res[m * N + n];
                    v1 += res[m * N + n + 1];
                }
                *(float2*)&C[m * N + n] = make_float2(v0, v1);
            }
        }
    }
}

// ---------------- kernel 3: tf32 flash attention ---------------------------
// BQ=64 (4 warps x 16 rows), BK=64, d=48.
// qkv: [B*N, 1152], col = which*384 + head*48 + dd.  attn: [B*N, 384]
#define QS_STRIDE 52
#define VS_STRIDE 56
#define PS_STRIDE 68
__global__ void __launch_bounds__(128)
k_attn(const float* __restrict__ qkv, float* __restrict__ attn)
{
    __shared__ float Qs[64 * QS_STRIDE];   // Q, tf32 bits, pre-scaled
    __shared__ float KP[64 * PS_STRIDE];   // K (stride 52) aliased with P (stride 68)
    __shared__ float Vs[64 * VS_STRIDE];   // V, tf32 bits

    const int bh = blockIdx.y;
    const int bb = bh >> 3, hh = bh & 7;
    const float* base = qkv + (size_t)bb * NTOK * QKVC + hh * HDIM;
    const int q0 = blockIdx.x * 64;
    const int tid = threadIdx.x;
    const int w = tid >> 5, lane = tid & 31;
    const int g = lane >> 2, tg = lane & 3;
    const int wrow0 = w * 16;

    // load Q tile (scaled, tf32)
    for (int i = tid; i < 64 * 12; i += 128) {
        int r = i / 12, c4 = (i % 12) * 4;
        float4 v = *(const float4*)(base + (size_t)(q0 + r) * QKVC + c4);
        float4 t = make_float4(f2t(v.x * ATT_SCALE), f2t(v.y * ATT_SCALE),
                               f2t(v.z * ATT_SCALE), f2t(v.w * ATT_SCALE));
        *(float4*)&Qs[r * QS_STRIDE + c4] = t;
    }

    float oacc[6][4];
    #pragma unroll
    for (int i = 0; i < 6; i++)
        #pragma unroll
        for (int j = 0; j < 4; j++) oacc[i][j] = 0.f;
    float mA = -1e30f, mB = -1e30f, lA = 0.f, lB = 0.f;

    for (int kt = 0; kt < NTOK / 64; kt++) {
        const int k0 = kt * 64;
        __syncthreads();   // prev tile fully consumed (also covers Q load on iter 0)

        // load K (stride 52) and V (stride 56), tf32 bits
        for (int i = tid; i < 64 * 12; i += 128) {
            int r = i / 12, c4 = (i % 12) * 4;
            size_t off = (size_t)(k0 + r) * QKVC + c4;
            float4 kv = *(const float4*)(base + off + DIM);
            float4 vv = *(const float4*)(base + off + 2 * DIM);
            *(float4*)&KP[r * QS_STRIDE + c4] =
                make_float4(f2t(kv.x), f2t(kv.y), f2t(kv.z), f2t(kv.w));
            *(float4*)&Vs[r * VS_STRIDE + c4] =
                make_float4(f2t(vv.x), f2t(vv.y), f2t(vv.z), f2t(vv.w));
        }
        __syncthreads();

        // S = Q @ K^T  (per warp: 16 x 64)
        float sacc[8][4];
        #pragma unroll
        for (int ns = 0; ns < 8; ns++)
            #pragma unroll
            for (int q = 0; q < 4; q++) sacc[ns][q] = 0.f;
        #pragma unroll
        for (int kc = 0; kc < 6; kc++) {
            float aq[4];
            int r = wrow0 + g, k = kc * 8 + tg;
            aq[0] = Qs[r * QS_STRIDE + k];
            aq[1] = Qs[(r + 8) * QS_STRIDE + k];
            aq[2] = Qs[r * QS_STRIDE + k + 4];
            aq[3] = Qs[(r + 8) * QS_STRIDE + k + 4];
            #pragma unroll
            for (int ns = 0; ns < 8; ns++) {
                float bk[2];
                int n = ns * 8 + g;
                bk[0] = KP[n * QS_STRIDE + k];
                bk[1] = KP[n * QS_STRIDE + k + 4];
                mma8(sacc[ns], aq, bk);
            }
        }

        // online softmax (register C-fragment layout)
        float rmaxA = -1e30f, rmaxB = -1e30f;
        #pragma unroll
        for (int ns = 0; ns < 8; ns++) {
            rmaxA = fmaxf(rmaxA, fmaxf(sacc[ns][0], sacc[ns][1]));
            rmaxB = fmaxf(rmaxB, fmaxf(sacc[ns][2], sacc[ns][3]));
        }
        rmaxA = fmaxf(rmaxA, __shfl_xor_sync(0xffffffffu, rmaxA, 1));
        rmaxA = fmaxf(rmaxA, __shfl_xor_sync(0xffffffffu, rmaxA, 2));
        rmaxB = fmaxf(rmaxB, __shfl_xor_sync(0xffffffffu, rmaxB, 1));
        rmaxB = fmaxf(rmaxB, __shfl_xor_sync(0xffffffffu, rmaxB, 2));

        float mAn = fmaxf(mA, rmaxA), mBn = fmaxf(mB, rmaxB);
        float fA = __expf(mA - mAn), fB = __expf(mB - mBn);
        mA = mAn; mB = mBn;

        float sumA = 0.f, sumB = 0.f;
        #pragma unroll
        for (int ns = 0; ns < 8; ns++) {
            sacc[ns][0] = __expf(sacc[ns][0] - mA);
            sacc[ns][1] = __expf(sacc[ns][1] - mA);
            sacc[ns][2] = __expf(sacc[ns][2] - mB);
            sacc[ns][3] = __expf(sacc[ns][3] - mB);
            sumA += sacc[ns][0] + sacc[ns][1];
            sumB += sacc[ns][2] + sacc[ns][3];
        }
        sumA += __shfl_xor_sync(0xffffffffu, sumA, 1);
        sumA += __shfl_xor_sync(0xffffffffu, sumA, 2);
        sumB += __shfl_xor_sync(0xffffffffu, sumB, 1);
        sumB += __shfl_xor_sync(0xffffffffu, sumB, 2);
        lA = lA * fA + sumA;
        lB = lB * fB + sumB;

        #pragma unroll
        for (int ns = 0; ns < 6; ns++) {
            oacc[ns][0] *= fA; oacc[ns][1] *= fA;
            oacc[ns][2] *= fB; oacc[ns][3] *= fB;
        }

        __syncthreads();   // all warps done reading K before overwriting with P

        // store P (tf32) into KP with stride 68; rows owned per-warp
        #pragma unroll
        for (int ns = 0; ns < 8; ns++) {
            int r = wrow0 + g, c = ns * 8 + tg * 2;
            *(float2*)&KP[r * PS_STRIDE + c] =
                make_float2(f2t(sacc[ns][0]), f2t(sacc[ns][1]));
            *(float2*)&KP[(r + 8) * PS_STRIDE + c] =
                make_float2(f2t(sacc[ns][2]), f2t(sacc[ns][3]));
        }
        __syncwarp();

        // O += P @ V  (per warp: 16 x 48, K=64)
        #pragma unroll
        for (int kc = 0; kc < 8; kc++) {
            float ap[4];
            int r = wrow0 + g, k = kc * 8 + tg;
            ap[0] = KP[r * PS_STRIDE + k];
            ap[1] = KP[(r + 8) * PS_STRIDE + k];
            ap[2] = KP[r * PS_STRIDE + k + 4];
            ap[3] = KP[(r + 8) * PS_STRIDE + k + 4];
            #pragma unroll
            for (int ns = 0; ns < 6; ns++) {
                float bv[2];
                int n = ns * 8 + g;
                bv[0] = Vs[(kc * 8 + tg) * VS_STRIDE + n];
                bv[1] = Vs[(kc * 8 + tg + 4) * VS_STRIDE + n];
                mma8(oacc[ns], ap, bv);
            }
        }
    }

    // write O / l
    float invA = 1.f / lA, invB = 1.f / lB;
    size_t rowA = (size_t)bb * NTOK + q0 + wrow0 + g;
    #pragma unroll
    for (int ns = 0; ns < 6; ns++) {
        int col = hh * HDIM + ns * 8 + tg * 2;
        *(float2*)&attn[rowA * DIM + col] =
            make_float2(oacc[ns][0] * invA, oacc[ns][1] * invA);
        *(float2*)&attn[(rowA + 8) * DIM + col] =
            make_float2(oacc[ns][2] * invB, oacc[ns][3] * invB);
    }
}

// --------------------------- kernel 4: LN ---------------------------------
__global__ void k_ln(const float* __restrict__ in, const float* __restrict__ g,
                     const float* __restrict__ b, float* __restrict__ out)
{
    const int row = blockIdx.x;
    const float* p = in + (size_t)row * DIM;
    const int t = threadIdx.x;
    float v0 = p[t], v1 = p[t + 128], v2 = p[t + 256];
    float s = v0 + v1 + v2;

    __shared__ float red[4];
    #pragma unroll
    for (int o = 16; o; o >>= 1) s += __shfl_xor_sync(0xffffffffu, s, o);
    if ((t & 31) == 0) red[t >> 5] = s;
    __syncthreads();
    float mu = (red[0] + red[1] + red[2] + red[3]) * (1.f / DIM);

    float d0 = v0 - mu, d1 = v1 - mu, d2 = v2 - mu;
    float q = d0 * d0 + d1 * d1 + d2 * d2;
    __syncthreads();
    #pragma unroll
    for (int o = 16; o; o >>= 1) q += __shfl_xor_sync(0xffffffffu, q, o);
    if ((t & 31) == 0) red[t >> 5] = q;
    __syncthreads();
    float rstd = rsqrtf((red[0] + red[1] + red[2] + red[3]) * (1.f / DIM) + 1e-6f);

    float* po = out + (size_t)row * DIM;
    po[t]       = d0 * rstd * g[t]       + b[t];
    po[t + 128] = d1 * rstd * g[t + 128] + b[t + 128];
    po[t + 256] = d2 * rstd * g[t + 256] + b[t + 256];
}

// ---------------------- kernel 5: transpose back ---------------------------
__global__ void k_transpose_out(const float* __restrict__ h, float* __restrict__ out)
{
    __shared__ float tile[TT][DIM + 1];
    const int tilesPerBatch = NTOK / TT;
    const int bb = blockIdx.x / tilesPerBatch;
    const int n0 = (blockIdx.x % tilesPerBatch) * TT;

    for (int idx = threadIdx.x; idx < DIM * TT; idx += blockDim.x) {
        int t = idx / DIM, c = idx % DIM;
        tile[t][c] = h[((size_t)bb * NTOK + n0 + t) * DIM + c];
    }
    __syncthreads();
    float* ob = out + (size_t)bb * DIM * NTOK;
    for (int idx = threadIdx.x; idx < DIM * TT; idx += blockDim.x) {
        int c = idx / TT, t = idx % TT;
        ob[(size_t)c * NTOK + n0 + t] = tile[t][c];
    }
}

// ------------------------------- launch ------------------------------------
extern "C" void kernel_launch(void* const* d_in, const int* in_sizes, int n_in,
                              void* d_out, int out_size)
{
    const float* x    = (const float*)d_in[0];
    const float* g1   = (const float*)d_in[1];
    const float* b1   = (const float*)d_in[2];
    const float* Wqkv = (const float*)d_in[3];
    const float* Wo   = (const float*)d_in[4];
    const float* bo   = (const float*)d_in[5];
    const float* g2   = (const float*)d_in[6];
    const float* b2   = (const float*)d_in[7];
    const float* W1   = (const float*)d_in[8];
    const float* b1m  = (const float*)d_in[9];
    const float* W2   = (const float*)d_in[10];
    const float* b2m  = (const float*)d_in[11];
    float* out = (float*)d_out;

    float *h, *hn, *qkv, *att, *mlp;
    cudaGetSymbolAddress((void**)&h,   g_h);
    cudaGetSymbolAddress((void**)&hn,  g_hn);
    cudaGetSymbolAddress((void**)&qkv, g_qkv);
    cudaGetSymbolAddress((void**)&att, g_att);
    cudaGetSymbolAddress((void**)&mlp, g_mlp);

    // 1. transpose + LN1
    k_transpose_ln<<<MTOT / TT, 256>>>(x, g1, b1, h, hn);
    // 2. QKV = hn @ Wqkv
    k_mmagemm<128, false, false, false><<<dim3(QKVC / 128, MTOT / 128), 256>>>(
        hn, Wqkv, nullptr, nullptr, qkv, MTOT, QKVC, DIM);
    // 3. attention
    k_attn<<<dim3(NTOK / 64, BATCH * NHEADS), 128>>>(qkv, att);
    // 4. h += att @ Wo + bo
    k_mmagemm<64, true, false, true><<<dim3(DIM / 64, MTOT / 128), 256>>>(
        att, Wo, bo, h, h, MTOT, DIM, DIM);
    // 5. LN2
    k_ln<<<MTOT, 128>>>(h, g2, b2, hn);
    // 6. mlp = gelu(hn @ W1 + b1m)
    k_mmagemm<128, true, true, false><<<dim3(MLPH / 128, MTOT / 128), 256>>>(
        hn, W1, b1m, nullptr, mlp, MTOT, MLPH, DIM);
    // 7. h += mlp @ W2 + b2m
    k_mmagemm<64, true, false, true><<<dim3(DIM / 64, MTOT / 128), 256>>>(
        mlp, W2, b2m, h, h, MTOT, DIM, MLPH);
    // 8. transpose back
    k_transpose_out<<<MTOT / TT, 256>>>(h, out);
}

// round 3
// speedup vs baseline: 6.7353x; 1.6177x over previous
#include <cuda_runtime.h>
#include <cuda_bf16.h>
#include <cstdint>
#include <math.h>

// ---------------------------------------------------------------------------
// TransformerBlock: B=2, C=384, N=2048 tokens/batch, H=8 heads, d=48
// MLP hidden 1536, exact-erf GELU, LN eps 1e-6. fp32 I/O + residual stream,
// bf16 tensor-core math (mma.m16n8k16).
// ---------------------------------------------------------------------------

#define BATCH   2
#define DIM     384
#define NTOK    2048
#define MTOT    (BATCH * NTOK)  // 4096
#define NHEADS  8
#define HDIM    48
#define QKVC    (3 * DIM)       // 1152
#define MLPH    1536
#define ATT_SCALE 0.14433756729740643f

// ----------------------------- scratch ------------------------------------
__device__ float         g_h   [MTOT * DIM];     // residual stream (fp32)
__device__ __nv_bfloat16 g_hnb [MTOT * DIM];     // normalized (bf16)
__device__ __nv_bfloat16 g_qkvb[MTOT * QKVC];
__device__ __nv_bfloat16 g_attb[MTOT * DIM];
__device__ __nv_bfloat16 g_mlpb[MTOT * MLPH];
// transposed bf16 weights [N][K]
__device__ __nv_bfloat16 g_wqkv[QKVC * DIM];
__device__ __nv_bfloat16 g_wo  [DIM * DIM];
__device__ __nv_bfloat16 g_w1  [MLPH * DIM];
__device__ __nv_bfloat16 g_w2  [DIM * MLPH];

// --------------------------- mma helpers -----------------------------------
__device__ __forceinline__ void mma16(float* c, const uint32_t* a,
                                      uint32_t b0, uint32_t b1) {
    asm volatile(
        "mma.sync.aligned.m16n8k16.row.col.f32.bf16.bf16.f32 "
        "{%0,%1,%2,%3}, {%4,%5,%6,%7}, {%8,%9}, {%0,%1,%2,%3};\n"
        : "+f"(c[0]), "+f"(c[1]), "+f"(c[2]), "+f"(c[3])
        : "r"(a[0]), "r"(a[1]), "r"(a[2]), "r"(a[3]), "r"(b0), "r"(b1));
}
__device__ __forceinline__ uint32_t packbf(float x, float y) {
    __nv_bfloat162 h = __floats2bfloat162_rn(x, y);
    return *(uint32_t*)&h;
}

// ------------------ weight prep: fp32 [R][C] -> bf16 [C][R] ----------------
__global__ void k_wprep(const float* __restrict__ in, __nv_bfloat16* __restrict__ out,
                        int R, int C)
{
    __shared__ float t[32][33];
    const int c = blockIdx.x * 32 + threadIdx.x;
    #pragma unroll
    for (int j = 0; j < 4; j++) {
        int r = blockIdx.y * 32 + threadIdx.y + j * 8;
        t[threadIdx.y + j * 8][threadIdx.x] = in[(size_t)r * C + c];
    }
    __syncthreads();
    const int r2 = blockIdx.y * 32 + threadIdx.x;
    #pragma unroll
    for (int j = 0; j < 4; j++) {
        int c2 = blockIdx.x * 32 + threadIdx.y + j * 8;
        out[(size_t)c2 * R + r2] = __float2bfloat16(t[threadIdx.x][threadIdx.y + j * 8]);
    }
}

// ------------------------ kernel 1: transpose + LN1 ------------------------
#define TT 16
__global__ void k_transpose_ln(const float* __restrict__ x,
                               const float* __restrict__ g,
                               const float* __restrict__ b,
                               float* __restrict__ h,
                               __nv_bfloat16* __restrict__ hn)
{
    __shared__ float tile[TT][DIM + 1];
    const int tilesPerBatch = NTOK / TT;
    const int bb = blockIdx.x / tilesPerBatch;
    const int n0 = (blockIdx.x % tilesPerBatch) * TT;
    const float* xb = x + (size_t)bb * DIM * NTOK;

    for (int idx = threadIdx.x; idx < DIM * TT; idx += blockDim.x) {
        int c = idx / TT, t = idx % TT;
        tile[t][c] = xb[(size_t)c * NTOK + n0 + t];
    }
    __syncthreads();

    const int wid = threadIdx.x >> 5, lane = threadIdx.x & 31;
    for (int t = wid; t < TT; t += (int)(blockDim.x >> 5)) {
        float s = 0.f;
        #pragma unroll
        for (int c = lane; c < DIM; c += 32) s += tile[t][c];
        #pragma unroll
        for (int o = 16; o; o >>= 1) s += __shfl_xor_sync(0xffffffffu, s, o);
        float mu = s * (1.f / DIM);
        float vs = 0.f;
        #pragma unroll
        for (int c = lane; c < DIM; c += 32) { float d = tile[t][c] - mu; vs += d * d; }
        #pragma unroll
        for (int o = 16; o; o >>= 1) vs += __shfl_xor_sync(0xffffffffu, vs, o);
        float rstd = rsqrtf(vs * (1.f / DIM) + 1e-6f);
        size_t row = ((size_t)bb * NTOK + n0 + t) * DIM;
        for (int c = lane; c < DIM; c += 32) {
            float v = tile[t][c];
            h[row + c]  = v;
            hn[row + c] = __float2bfloat16((v - mu) * rstd * g[c] + b[c]);
        }
    }
}

// ----------------- kernel 2: bf16 tensor-core GEMM -------------------------
// C[M,N] = A[M,K] @ B[K,N] with B given transposed bf16 Bt[N][K].
// BN=64, BK=32, 8 warps. BM=128: 4x2 warps (warp 32x32). BM=64: 2x4 (32x16).
template<int BM, bool BIAS, bool GELU, bool RES, bool OUTBF>
__global__ void __launch_bounds__(256)
k_gemm(const __nv_bfloat16* __restrict__ A, const __nv_bfloat16* __restrict__ Bt,
       const float* __restrict__ bias, const float* __restrict__ res,
       void* __restrict__ Cout, int M, int N, int K)
{
    constexpr int BN = 64, BK = 32;
    constexpr int SA = BK + 8;              // 40 bf16 row stride (20 words: CF)
    constexpr int MW = BM / 32;             // m-warps
    constexpr int WN = BN / (8 / MW);       // warp n-tile
    constexpr int NS = WN / 8;              // n-steps
    __shared__ __nv_bfloat16 As[2][BM * SA];
    __shared__ __nv_bfloat16 Bs[2][BN * SA];

    const int tid = threadIdx.x;
    const int m0 = blockIdx.y * BM, n0 = blockIdx.x * BN;
    const int wid = tid >> 5, lane = tid & 31;
    const int g = lane >> 2, tg = lane & 3;
    const int wm0 = (wid % MW) * 32;
    const int wn0 = (wid / MW) * WN;

    float acc[2][NS][4];
    #pragma unroll
    for (int i = 0; i < 2; i++)
        #pragma unroll
        for (int j = 0; j < NS; j++)
            #pragma unroll
            for (int q = 0; q < 4; q++) acc[i][j][q] = 0.f;

    const int a_r = tid >> 2;               // 0..63
    const int a_c = (tid & 3) * 8;
    const __nv_bfloat16* Ap = A  + (size_t)(m0 + a_r) * K + a_c;
    const __nv_bfloat16* Bp = Bt + (size_t)(n0 + a_r) * K + a_c;

    uint4 ra0, ra1 = make_uint4(0, 0, 0, 0), rb;
    ra0 = *(const uint4*)Ap;
    if (BM == 128) ra1 = *(const uint4*)(Ap + (size_t)64 * K);
    rb = *(const uint4*)Bp;

    *(uint4*)&As[0][a_r * SA + a_c] = ra0;
    if (BM == 128) *(uint4*)&As[0][(a_r + 64) * SA + a_c] = ra1;
    *(uint4*)&Bs[0][a_r * SA + a_c] = rb;
    __syncthreads();

    const int ntiles = K / BK;
    for (int t = 0; t < ntiles; t++) {
        const int cur = t & 1;
        const bool more = (t + 1 < ntiles);
        if (more) {
            ra0 = *(const uint4*)(Ap + (t + 1) * BK);
            if (BM == 128) ra1 = *(const uint4*)(Ap + (size_t)64 * K + (t + 1) * BK);
            rb = *(const uint4*)(Bp + (t + 1) * BK);
        }

        #pragma unroll
        for (int kk = 0; kk < 2; kk++) {
            uint32_t af[2][4];
            #pragma unroll
            for (int ms = 0; ms < 2; ms++) {
                int r = wm0 + ms * 16 + g;
                af[ms][0] = *(const uint32_t*)&As[cur][r * SA + kk * 16 + 2 * tg];
                af[ms][1] = *(const uint32_t*)&As[cur][(r + 8) * SA + kk * 16 + 2 * tg];
                af[ms][2] = *(const uint32_t*)&As[cur][r * SA + kk * 16 + 2 * tg + 8];
                af[ms][3] = *(const uint32_t*)&As[cur][(r + 8) * SA + kk * 16 + 2 * tg + 8];
            }
            #pragma unroll
            for (int ns = 0; ns < NS; ns++) {
                int n = wn0 + ns * 8 + g;
                uint32_t b0 = *(const uint32_t*)&Bs[cur][n * SA + kk * 16 + 2 * tg];
                uint32_t b1 = *(const uint32_t*)&Bs[cur][n * SA + kk * 16 + 2 * tg + 8];
                #pragma unroll
                for (int ms = 0; ms < 2; ms++) mma16(acc[ms][ns], af[ms], b0, b1);
            }
        }

        if (more) {
            *(uint4*)&As[cur ^ 1][a_r * SA + a_c] = ra0;
            if (BM == 128) *(uint4*)&As[cur ^ 1][(a_r + 64) * SA + a_c] = ra1;
            *(uint4*)&Bs[cur ^ 1][a_r * SA + a_c] = rb;
        }
        __syncthreads();
    }

    // epilogue
    #pragma unroll
    for (int ms = 0; ms < 2; ms++) {
        #pragma unroll
        for (int rr = 0; rr < 2; rr++) {
            size_t m = (size_t)m0 + wm0 + ms * 16 + g + rr * 8;
            #pragma unroll
            for (int ns = 0; ns < NS; ns++) {
                int n = n0 + wn0 + ns * 8 + tg * 2;
                float v0 = acc[ms][ns][rr * 2 + 0];
                float v1 = acc[ms][ns][rr * 2 + 1];
                if (BIAS) { v0 += bias[n]; v1 += bias[n + 1]; }
                if (GELU) {
                    v0 = 0.5f * v0 * (1.f + erff(v0 * 0.70710678118654752f));
                    v1 = 0.5f * v1 * (1.f + erff(v1 * 0.70710678118654752f));
                }
                if (RES) {
                    v0 += res[m * N + n];
                    v1 += res[m * N + n + 1];
                }
                if (OUTBF) {
                    *(__nv_bfloat162*)((__nv_bfloat16*)Cout + m * N + n) =
                        __floats2bfloat162_rn(v0, v1);
                } else {
                    *(float2*)((float*)Cout + m * N + n) = make_float2(v0, v1);
                }
            }
        }
    }
}

// ---------------- kernel 3: bf16 flash attention ---------------------------
// BQ=64 (4 warps x 16 rows), BK=64, d=48. P stays in registers.
__global__ void __launch_bounds__(128)
k_attn(const __nv_bfloat16* __restrict__ qkv, __nv_bfloat16* __restrict__ attn)
{
    constexpr int SQ = 56;   // 28-word stride: conflict-free
    constexpr int SV = 72;   // 36-word stride: conflict-free
    __shared__ __nv_bfloat16 Qs[64 * SQ];
    __shared__ __nv_bfloat16 Ks[64 * SQ];
    __shared__ __nv_bfloat16 Vt[48 * SV];   // V transposed: [d][token]

    const int bh = blockIdx.y;
    const int bb = bh >> 3, hh = bh & 7;
    const __nv_bfloat16* base = qkv + (size_t)bb * NTOK * QKVC + hh * HDIM;
    const int q0 = blockIdx.x * 64;
    const int tid = threadIdx.x;
    const int w = tid >> 5, lane = tid & 31;
    const int g = lane >> 2, tg = lane & 3;
    const int wrow0 = w * 16;

    #pragma unroll
    for (int j = 0; j < 3; j++) {
        int idx = tid + j * 128;
        int r = idx / 6, c8 = (idx % 6) * 8;
        *(uint4*)&Qs[r * SQ + c8] = *(const uint4*)(base + (size_t)(q0 + r) * QKVC + c8);
    }

    float oacc[6][4];
    #pragma unroll
    for (int i = 0; i < 6; i++)
        #pragma unroll
        for (int j = 0; j < 4; j++) oacc[i][j] = 0.f;
    float mA = -1e30f, mB = -1e30f, lA = 0.f, lB = 0.f;

    for (int kt = 0; kt < NTOK / 64; kt++) {
        const int k0 = kt * 64;
        __syncthreads();   // prev tile consumed (covers Q load on iter 0)

        #pragma unroll
        for (int j = 0; j < 3; j++) {
            int idx = tid + j * 128;
            int r = idx / 6, c8 = (idx % 6) * 8;
            size_t off = (size_t)(k0 + r) * QKVC + c8;
            *(uint4*)&Ks[r * SQ + c8] = *(const uint4*)(base + off + DIM);
            union { uint4 u; __nv_bfloat16 b[8]; } vb;
            vb.u = *(const uint4*)(base + off + 2 * DIM);
            #pragma unroll
            for (int d = 0; d < 8; d++) Vt[(c8 + d) * SV + r] = vb.b[d];
        }
        __syncthreads();

        // S = Q @ K^T (per warp 16 x 64)
        float sacc[8][4];
        #pragma unroll
        for (int ns = 0; ns < 8; ns++)
            #pragma unroll
            for (int q = 0; q < 4; q++) sacc[ns][q] = 0.f;
        #pragma unroll
        for (int kc = 0; kc < 3; kc++) {
            uint32_t aq[4];
            int r = wrow0 + g, c = kc * 16 + 2 * tg;
            aq[0] = *(const uint32_t*)&Qs[r * SQ + c];
            aq[1] = *(const uint32_t*)&Qs[(r + 8) * SQ + c];
            aq[2] = *(const uint32_t*)&Qs[r * SQ + c + 8];
            aq[3] = *(const uint32_t*)&Qs[(r + 8) * SQ + c + 8];
            #pragma unroll
            for (int ns = 0; ns < 8; ns++) {
                int n = ns * 8 + g;
                uint32_t b0 = *(const uint32_t*)&Ks[n * SQ + c];
                uint32_t b1 = *(const uint32_t*)&Ks[n * SQ + c + 8];
                mma16(sacc[ns], aq, b0, b1);
            }
        }
        #pragma unroll
        for (int ns = 0; ns < 8; ns++)
            #pragma unroll
            for (int q = 0; q < 4; q++) sacc[ns][q] *= ATT_SCALE;

        // online softmax on C-fragments (rows g / g+8)
        float rmaxA = -1e30f, rmaxB = -1e30f;
        #pragma unroll
        for (int ns = 0; ns < 8; ns++) {
            rmaxA = fmaxf(rmaxA, fmaxf(sacc[ns][0], sacc[ns][1]));
            rmaxB = fmaxf(rmaxB, fmaxf(sacc[ns][2], sacc[ns][3]));
        }
        rmaxA = fmaxf(rmaxA, __shfl_xor_sync(0xffffffffu, rmaxA, 1));
        rmaxA = fmaxf(rmaxA, __shfl_xor_sync(0xffffffffu, rmaxA, 2));
        rmaxB = fmaxf(rmaxB, __shfl_xor_sync(0xffffffffu, rmaxB, 1));
        rmaxB = fmaxf(rmaxB, __shfl_xor_sync(0xffffffffu, rmaxB, 2));

        float mAn = fmaxf(mA, rmaxA), mBn = fmaxf(mB, rmaxB);
        float fA = __expf(mA - mAn), fB = __expf(mB - mBn);
        mA = mAn; mB = mBn;

        float sumA = 0.f, sumB = 0.f;
        #pragma unroll
        for (int ns = 0; ns < 8; ns++) {
            sacc[ns][0] = __expf(sacc[ns][0] - mA);
            sacc[ns][1] = __expf(sacc[ns][1] - mA);
            sacc[ns][2] = __expf(sacc[ns][2] - mB);
            sacc[ns][3] = __expf(sacc[ns][3] - mB);
            sumA += sacc[ns][0] + sacc[ns][1];
            sumB += sacc[ns][2] + sacc[ns][3];
        }
        sumA += __shfl_xor_sync(0xffffffffu, sumA, 1);
        sumA += __shfl_xor_sync(0xffffffffu, sumA, 2);
        sumB += __shfl_xor_sync(0xffffffffu, sumB, 1);
        sumB += __shfl_xor_sync(0xffffffffu, sumB, 2);
        lA = lA * fA + sumA;
        lB = lB * fB + sumB;

        #pragma unroll
        for (int ns = 0; ns < 6; ns++) {
            oacc[ns][0] *= fA; oacc[ns][1] *= fA;
            oacc[ns][2] *= fB; oacc[ns][3] *= fB;
        }

        // O += P @ V : A-frags packed directly from S fragments (no smem!)
        #pragma unroll
        for (int kc = 0; kc < 4; kc++) {
            uint32_t ap[4];
            ap[0] = packbf(sacc[2 * kc][0],     sacc[2 * kc][1]);
            ap[1] = packbf(sacc[2 * kc][2],     sacc[2 * kc][3]);
            ap[2] = packbf(sacc[2 * kc + 1][0], sacc[2 * kc + 1][1]);
            ap[3] = packbf(sacc[2 * kc + 1][2], sacc[2 * kc + 1][3]);
            #pragma unroll
            for (int ns = 0; ns < 6; ns++) {
                int d = ns * 8 + g;
                uint32_t b0 = *(const uint32_t*)&Vt[d * SV + kc * 16 + 2 * tg];
                uint32_t b1 = *(const uint32_t*)&Vt[d * SV + kc * 16 + 2 * tg + 8];
                mma16(oacc[ns], ap, b0, b1);
            }
        }
    }

    float invA = 1.f / lA, invB = 1.f / lB;
    size_t rowA = (size_t)bb * NTOK + q0 + wrow0 + g;
    #pragma unroll
    for (int ns = 0; ns < 6; ns++) {
        int col = hh * HDIM + ns * 8 + tg * 2;
        *(__nv_bfloat162*)&attn[rowA * DIM + col] =
            __floats2bfloat162_rn(oacc[ns][0] * invA, oacc[ns][1] * invA);
        *(__nv_bfloat162*)&attn[(rowA + 8) * DIM + col] =
            __floats2bfloat162_rn(oacc[ns][2] * invB, oacc[ns][3] * invB);
    }
}

// --------------------------- kernel 4: LN ---------------------------------
__global__ void k_ln(const float* __restrict__ in, const float* __restrict__ g,
                     const float* __restrict__ b, __nv_bfloat16* __restrict__ out)
{
    const int row = blockIdx.x;
    const float* p = in + (size_t)row * DIM;
    const int t = threadIdx.x;
    float v0 = p[t], v1 = p[t + 128], v2 = p[t + 256];
    float s = v0 + v1 + v2;

    __shared__ float red[4];
    #pragma unroll
    for (int o = 16; o; o >>= 1) s += __shfl_xor_sync(0xffffffffu, s, o);
    if ((t & 31) == 0) red[t >> 5] = s;
    __syncthreads();
    float mu = (red[0] + red[1] + red[2] + red[3]) * (1.f / DIM);

    float d0 = v0 - mu, d1 = v1 - mu, d2 = v2 - mu;
    float q = d0 * d0 + d1 * d1 + d2 * d2;
    __syncthreads();
    #pragma unroll
    for (int o = 16; o; o >>= 1) q += __shfl_xor_sync(0xffffffffu, q, o);
    if ((t & 31) == 0) red[t >> 5] = q;
    __syncthreads();
    float rstd = rsqrtf((red[0] + red[1] + red[2] + red[3]) * (1.f / DIM) + 1e-6f);

    __nv_bfloat16* po = out + (size_t)row * DIM;
    po[t]       = __float2bfloat16(d0 * rstd * g[t]       + b[t]);
    po[t + 128] = __float2bfloat16(d1 * rstd * g[t + 128] + b[t + 128]);
    po[t + 256] = __float2bfloat16(d2 * rstd * g[t + 256] + b[t + 256]);
}

// ---------------------- kernel 5: transpose back ---------------------------
__global__ void k_transpose_out(const float* __restrict__ h, float* __restrict__ out)
{
    __shared__ float tile[TT][DIM + 1];
    const int tilesPerBatch = NTOK / TT;
    const int bb = blockIdx.x / tilesPerBatch;
    const int n0 = (blockIdx.x % tilesPerBatch) * TT;

    for (int idx = threadIdx.x; idx < DIM * TT; idx += blockDim.x) {
        int t = idx / DIM, c = idx % DIM;
        tile[t][c] = h[((size_t)bb * NTOK + n0 + t) * DIM + c];
    }
    __syncthreads();
    float* ob = out + (size_t)bb * DIM * NTOK;
    for (int idx = threadIdx.x; idx < DIM * TT; idx += blockDim.x) {
        int c = idx / TT, t = idx % TT;
        ob[(size_t)c * NTOK + n0 + t] = tile[t][c];
    }
}

// ------------------------------- launch ------------------------------------
extern "C" void kernel_launch(void* const* d_in, const int* in_sizes, int n_in,
                              void* d_out, int out_size)
{
    const float* x    = (const float*)d_in[0];
    const float* g1   = (const float*)d_in[1];
    const float* b1   = (const float*)d_in[2];
    const float* Wqkv = (const float*)d_in[3];
    const float* Wo   = (const float*)d_in[4];
    const float* bo   = (const float*)d_in[5];
    const float* g2   = (const float*)d_in[6];
    const float* b2   = (const float*)d_in[7];
    const float* W1   = (const float*)d_in[8];
    const float* b1m  = (const float*)d_in[9];
    const float* W2   = (const float*)d_in[10];
    const float* b2m  = (const float*)d_in[11];
    float* out = (float*)d_out;

    float* h;
    __nv_bfloat16 *hnb, *qkvb, *attb, *mlpb, *wqkv, *wo, *w1, *w2;
    cudaGetSymbolAddress((void**)&h,    g_h);
    cudaGetSymbolAddress((void**)&hnb,  g_hnb);
    cudaGetSymbolAddress((void**)&qkvb, g_qkvb);
    cudaGetSymbolAddress((void**)&attb, g_attb);
    cudaGetSymbolAddress((void**)&mlpb, g_mlpb);
    cudaGetSymbolAddress((void**)&wqkv, g_wqkv);
    cudaGetSymbolAddress((void**)&wo,   g_wo);
    cudaGetSymbolAddress((void**)&w1,   g_w1);
    cudaGetSymbolAddress((void**)&w2,   g_w2);

    dim3 tb(32, 8);
    // weight prep (transpose + bf16)
    k_wprep<<<dim3(QKVC / 32, DIM / 32), tb>>>(Wqkv, wqkv, DIM, QKVC);
    k_wprep<<<dim3(DIM / 32, DIM / 32),  tb>>>(Wo,   wo,   DIM, DIM);
    k_wprep<<<dim3(MLPH / 32, DIM / 32), tb>>>(W1,   w1,   DIM, MLPH);
    k_wprep<<<dim3(DIM / 32, MLPH / 32), tb>>>(W2,   w2,   MLPH, DIM);

    // 1. transpose + LN1
    k_transpose_ln<<<MTOT / TT, 256>>>(x, g1, b1, h, hnb);
    // 2. qkv = hn @ Wqkv  (bf16 out)
    k_gemm<128, false, false, false, true><<<dim3(QKVC / 64, MTOT / 128), 256>>>(
        hnb, wqkv, nullptr, nullptr, qkvb, MTOT, QKVC, DIM);
    // 3. attention
    k_attn<<<dim3(NTOK / 64, BATCH * NHEADS), 128>>>(qkvb, attb);
    // 4. h += att @ Wo + bo  (fp32 out)
    k_gemm<64, true, false, true, false><<<dim3(DIM / 64, MTOT / 64), 256>>>(
        attb, wo, bo, h, h, MTOT, DIM, DIM);
    // 5. LN2 (bf16 out)
    k_ln<<<MTOT, 128>>>(h, g2, b2, hnb);
    // 6. mlp = gelu(hn @ W1 + b1m)  (bf16 out)
    k_gemm<128, true, true, false, true><<<dim3(MLPH / 64, MTOT / 128), 256>>>(
        hnb, w1, b1m, nullptr, mlpb, MTOT, MLPH, DIM);
    // 7. h += mlp @ W2 + b2m  (fp32 out)
    k_gemm<64, true, false, true, false><<<dim3(DIM / 64, MTOT / 64), 256>>>(
        mlpb, w2, b2m, h, h, MTOT, DIM, MLPH);
    // 8. transpose back
    k_transpose_out<<<MTOT / TT, 256>>>(h, out);
}

// round 4
// speedup vs baseline: 9.2160x; 1.3683x over previous
#include <cuda_runtime.h>
#include <cuda_bf16.h>
#include <cstdint>
#include <math.h>

// ---------------------------------------------------------------------------
// TransformerBlock: B=2, C=384, N=2048 tokens/batch, H=8 heads, d=48
// fp32 I/O + residual stream, bf16 mma.m16n8k16 + ldmatrix + cp.async.
// ---------------------------------------------------------------------------

#define BATCH   2
#define DIM     384
#define NTOK    2048
#define MTOT    (BATCH * NTOK)  // 4096
#define NHEADS  8
#define HDIM    48
#define QKVC    (3 * DIM)       // 1152
#define MLPH    1536
#define ATT_SCALE 0.14433756729740643f

// ----------------------------- scratch ------------------------------------
__device__ float         g_h   [MTOT * DIM];
__device__ __nv_bfloat16 g_hnb [MTOT * DIM];
__device__ __nv_bfloat16 g_qkvb[MTOT * QKVC];
__device__ __nv_bfloat16 g_attb[MTOT * DIM];
__device__ __nv_bfloat16 g_mlpb[MTOT * MLPH];
__device__ __nv_bfloat16 g_wqkv[QKVC * DIM];   // transposed [N][K]
__device__ __nv_bfloat16 g_wo  [DIM * DIM];
__device__ __nv_bfloat16 g_w1  [MLPH * DIM];
__device__ __nv_bfloat16 g_w2  [DIM * MLPH];

// --------------------------- asm helpers -----------------------------------
__device__ __forceinline__ void mma16(float* c, const uint32_t* a,
                                      uint32_t b0, uint32_t b1) {
    asm volatile(
        "mma.sync.aligned.m16n8k16.row.col.f32.bf16.bf16.f32 "
        "{%0,%1,%2,%3}, {%4,%5,%6,%7}, {%8,%9}, {%0,%1,%2,%3};\n"
        : "+f"(c[0]), "+f"(c[1]), "+f"(c[2]), "+f"(c[3])
        : "r"(a[0]), "r"(a[1]), "r"(a[2]), "r"(a[3]), "r"(b0), "r"(b1));
}
__device__ __forceinline__ uint32_t packbf(float x, float y) {
    __nv_bfloat162 h = __floats2bfloat162_rn(x, y);
    return *(uint32_t*)&h;
}
__device__ __forceinline__ uint32_t smaddr(const void* p) {
    return (uint32_t)__cvta_generic_to_shared(p);
}
__device__ __forceinline__ void ldsm4(uint32_t* r, uint32_t a) {
    asm volatile("ldmatrix.sync.aligned.m8n8.x4.shared.b16 {%0,%1,%2,%3}, [%4];"
                 : "=r"(r[0]), "=r"(r[1]), "=r"(r[2]), "=r"(r[3]) : "r"(a));
}
__device__ __forceinline__ void ldsm4t(uint32_t* r, uint32_t a) {
    asm volatile("ldmatrix.sync.aligned.m8n8.x4.trans.shared.b16 {%0,%1,%2,%3}, [%4];"
                 : "=r"(r[0]), "=r"(r[1]), "=r"(r[2]), "=r"(r[3]) : "r"(a));
}
__device__ __forceinline__ void cpasync16(uint32_t dst, const void* src) {
    asm volatile("cp.async.ca.shared.global [%0], [%1], 16;\n" :: "r"(dst), "l"(src));
}
__device__ __forceinline__ void cpcommit() { asm volatile("cp.async.commit_group;\n"); }
__device__ __forceinline__ void cpwait1()  { asm volatile("cp.async.wait_group 1;\n"); }
__device__ __forceinline__ void cpwait0()  { asm volatile("cp.async.wait_group 0;\n"); }

// ------------------ fused weight prep: fp32 [R][C] -> bf16 [C][R] ----------
__global__ void k_wprep_all(const float* __restrict__ Wqkv, const float* __restrict__ Wo,
                            const float* __restrict__ W1, const float* __restrict__ W2,
                            __nv_bfloat16* __restrict__ wqkv, __nv_bfloat16* __restrict__ wo,
                            __nv_bfloat16* __restrict__ w1, __nv_bfloat16* __restrict__ w2)
{
    __shared__ float t[32][33];
    int bid = blockIdx.x;
    const float* in; __nv_bfloat16* out; int R, C, rb, cb;
    if (bid < 432)       { int id = bid;        in = Wqkv; out = wqkv; R = 384;  C = 1152; cb = id % 36; rb = id / 36; }
    else if (bid < 576)  { int id = bid - 432;  in = Wo;   out = wo;   R = 384;  C = 384;  cb = id % 12; rb = id / 12; }
    else if (bid < 1152) { int id = bid - 576;  in = W1;   out = w1;   R = 384;  C = 1536; cb = id % 48; rb = id / 48; }
    else                 { int id = bid - 1152; in = W2;   out = w2;   R = 1536; C = 384;  cb = id % 12; rb = id / 12; }

    const int c = cb * 32 + threadIdx.x;
    #pragma unroll
    for (int j = 0; j < 4; j++) {
        int r = rb * 32 + threadIdx.y + j * 8;
        t[threadIdx.y + j * 8][threadIdx.x] = in[(size_t)r * C + c];
    }
    __syncthreads();
    const int r2 = rb * 32 + threadIdx.x;
    #pragma unroll
    for (int j = 0; j < 4; j++) {
        int c2 = cb * 32 + threadIdx.y + j * 8;
        out[(size_t)c2 * R + r2] = __float2bfloat16(t[threadIdx.x][threadIdx.y + j * 8]);
    }
}

// ------------------------ kernel 1: transpose + LN1 ------------------------
#define TT 16
__global__ void k_transpose_ln(const float* __restrict__ x,
                               const float* __restrict__ g,
                               const float* __restrict__ b,
                               float* __restrict__ h,
                               __nv_bfloat16* __restrict__ hn)
{
    __shared__ float tile[TT][DIM + 1];
    const int tilesPerBatch = NTOK / TT;
    const int bb = blockIdx.x / tilesPerBatch;
    const int n0 = (blockIdx.x % tilesPerBatch) * TT;
    const float* xb = x + (size_t)bb * DIM * NTOK;

    for (int idx = threadIdx.x; idx < DIM * TT; idx += blockDim.x) {
        int c = idx / TT, t = idx % TT;
        tile[t][c] = xb[(size_t)c * NTOK + n0 + t];
    }
    __syncthreads();

    const int wid = threadIdx.x >> 5, lane = threadIdx.x & 31;
    for (int t = wid; t < TT; t += (int)(blockDim.x >> 5)) {
        float s = 0.f;
        #pragma unroll
        for (int c = lane; c < DIM; c += 32) s += tile[t][c];
        #pragma unroll
        for (int o = 16; o; o >>= 1) s += __shfl_xor_sync(0xffffffffu, s, o);
        float mu = s * (1.f / DIM);
        float vs = 0.f;
        #pragma unroll
        for (int c = lane; c < DIM; c += 32) { float d = tile[t][c] - mu; vs += d * d; }
        #pragma unroll
        for (int o = 16; o; o >>= 1) vs += __shfl_xor_sync(0xffffffffu, vs, o);
        float rstd = rsqrtf(vs * (1.f / DIM) + 1e-6f);
        size_t row = ((size_t)bb * NTOK + n0 + t) * DIM;
        for (int c = lane; c < DIM; c += 32) {
            float v = tile[t][c];
            h[row + c]  = v;
            hn[row + c] = __float2bfloat16((v - mu) * rstd * g[c] + b[c]);
        }
    }
}

// ----------------- kernel 2: bf16 GEMM (ldmatrix + cp.async) ---------------
// C[M,N] = A[M,K] @ Bt[N][K]^T. BN=64, BK=32, 8 warps.
template<int BM, bool BIAS, bool GELU_, bool RES, bool OUTBF>
__global__ void __launch_bounds__(256)
k_gemm(const __nv_bfloat16* __restrict__ A, const __nv_bfloat16* __restrict__ Bt,
       const float* __restrict__ bias, const float* __restrict__ res,
       void* __restrict__ Cout, int M, int N, int K)
{
    constexpr int BN = 64, BK = 32;
    constexpr int SA = 40;                  // bf16 row stride (80B: CF for LDSM)
    constexpr int MW = BM / 32;             // 4 or 2
    constexpr int WN = BN / (8 / MW);       // 32 or 16
    constexpr int NS = WN / 8;              // 4 or 2
    __shared__ __nv_bfloat16 As[2][BM * SA];
    __shared__ __nv_bfloat16 Bs[2][BN * SA];

    const int tid = threadIdx.x;
    const int m0 = blockIdx.y * BM, n0 = blockIdx.x * BN;
    const int wid = tid >> 5, lane = tid & 31;
    const int g = lane >> 2, tg = lane & 3;
    const int wm0 = (wid % MW) * 32;
    const int wn0 = (wid / MW) * WN;
    const int lr = lane & 15, lk = (lane >> 4) * 8;

    float acc[2][NS][4];
    #pragma unroll
    for (int i = 0; i < 2; i++)
        #pragma unroll
        for (int j = 0; j < NS; j++)
            #pragma unroll
            for (int q = 0; q < 4; q++) acc[i][j][q] = 0.f;

    const int a_r = tid >> 2, a_c = (tid & 3) * 8;
    const __nv_bfloat16* Ap = A  + (size_t)(m0 + a_r) * K + a_c;
    const __nv_bfloat16* Bp = Bt + (size_t)(n0 + a_r) * K + a_c;

    uint32_t sA[2], sA2[2], sB[2];
    #pragma unroll
    for (int bset = 0; bset < 2; bset++) {
        sA[bset]  = smaddr(&As[bset][a_r * SA + a_c]);
        sA2[bset] = smaddr(&As[bset][(a_r + 64) * SA + a_c]);
        sB[bset]  = smaddr(&Bs[bset][a_r * SA + a_c]);
    }

    const int ntiles = K / BK;
    // prologue: tile 0
    cpasync16(sA[0], Ap);
    if (BM == 128) cpasync16(sA2[0], Ap + (size_t)64 * K);
    cpasync16(sB[0], Bp);
    cpcommit();

    for (int t = 0; t < ntiles; t++) {
        const int cur = t & 1;
        if (t + 1 < ntiles) {
            const __nv_bfloat16* an = Ap + (t + 1) * BK;
            const __nv_bfloat16* bn = Bp + (t + 1) * BK;
            cpasync16(sA[cur ^ 1], an);
            if (BM == 128) cpasync16(sA2[cur ^ 1], an + (size_t)64 * K);
            cpasync16(sB[cur ^ 1], bn);
            cpcommit();
            cpwait1();
        } else {
            cpwait0();
        }
        __syncthreads();

        #pragma unroll
        for (int kk = 0; kk < 2; kk++) {
            uint32_t af[2][4];
            #pragma unroll
            for (int ms = 0; ms < 2; ms++)
                ldsm4(af[ms], smaddr(&As[cur][(wm0 + ms * 16 + lr) * SA + kk * 16 + lk]));
            #pragma unroll
            for (int p = 0; p < NS / 2; p++) {
                uint32_t bf[4];
                ldsm4(bf, smaddr(&Bs[cur][(wn0 + p * 16 + lr) * SA + kk * 16 + lk]));
                #pragma unroll
                for (int ms = 0; ms < 2; ms++) {
                    mma16(acc[ms][2 * p],     af[ms], bf[0], bf[2]);
                    mma16(acc[ms][2 * p + 1], af[ms], bf[1], bf[3]);
                }
            }
        }
        __syncthreads();
    }

    // epilogue
    #pragma unroll
    for (int ms = 0; ms < 2; ms++) {
        #pragma unroll
        for (int rr = 0; rr < 2; rr++) {
            size_t m = (size_t)m0 + wm0 + ms * 16 + g + rr * 8;
            #pragma unroll
            for (int ns = 0; ns < NS; ns++) {
                int n = n0 + wn0 + ns * 8 + tg * 2;
                float v0 = acc[ms][ns][rr * 2 + 0];
                float v1 = acc[ms][ns][rr * 2 + 1];
                if (BIAS) { v0 += bias[n]; v1 += bias[n + 1]; }
                if (GELU_) {
                    v0 = 0.5f * v0 * (1.f + erff(v0 * 0.70710678118654752f));
                    v1 = 0.5f * v1 * (1.f + erff(v1 * 0.70710678118654752f));
                }
                if (RES) {
                    v0 += res[m * N + n];
                    v1 += res[m * N + n + 1];
                }
                if (OUTBF) {
                    *(__nv_bfloat162*)((__nv_bfloat16*)Cout + m * N + n) =
                        __floats2bfloat162_rn(v0, v1);
                } else {
                    *(float2*)((float*)Cout + m * N + n) = make_float2(v0, v1);
                }
            }
        }
    }
}

// ---------------- kernel 3: bf16 flash attention ---------------------------
// BQ=64 (4 warps x 16 rows), BK=64, d=48. ldmatrix(+trans for V), cp.async.
__global__ void __launch_bounds__(128)
k_attn(const __nv_bfloat16* __restrict__ qkv, __nv_bfloat16* __restrict__ attn)
{
    constexpr int SQ = 56;   // 112B stride: CF for LDSM
    __shared__ __nv_bfloat16 Qs[64 * SQ];
    __shared__ __nv_bfloat16 Ks[2][64 * SQ];
    __shared__ __nv_bfloat16 Vs[2][64 * SQ];

    const int bh = blockIdx.y;
    const int bb = bh >> 3, hh = bh & 7;
    const __nv_bfloat16* base = qkv + (size_t)bb * NTOK * QKVC + hh * HDIM;
    const int q0 = blockIdx.x * 64;
    const int tid = threadIdx.x;
    const int w = tid >> 5, lane = tid & 31;
    const int g = lane >> 2, tg = lane & 3;
    const int wrow0 = w * 16;
    const int lr = lane & 15, lk = (lane >> 4) * 8;

    // load-index mapping: 64 rows x 6 chunks of 8 bf16
    const int l_r = tid * 3 / 64;           // not used; use explicit loop below
    (void)l_r;

    // Q tile (vectorized, once)
    #pragma unroll
    for (int j = 0; j < 3; j++) {
        int idx = tid + j * 128;
        int r = idx / 6, c8 = (idx % 6) * 8;
        *(uint4*)&Qs[r * SQ + c8] = *(const uint4*)(base + (size_t)(q0 + r) * QKVC + c8);
    }

    float oacc[6][4];
    #pragma unroll
    for (int i = 0; i < 6; i++)
        #pragma unroll
        for (int j = 0; j < 4; j++) oacc[i][j] = 0.f;
    float mA = -1e30f, mB = -1e30f, lA = 0.f, lB = 0.f;

    const int r0i = (tid) / 6, c0i = ((tid) % 6) * 8;
    const int r1i = (tid + 128) / 6, c1i = ((tid + 128) % 6) * 8;
    const int r2i = (tid + 256) / 6, c2i = ((tid + 256) % 6) * 8;

    // prologue: K/V tile 0
    {
        size_t o0 = (size_t)r0i * QKVC + c0i, o1 = (size_t)r1i * QKVC + c1i, o2 = (size_t)r2i * QKVC + c2i;
        cpasync16(smaddr(&Ks[0][r0i * SQ + c0i]), base + o0 + DIM);
        cpasync16(smaddr(&Ks[0][r1i * SQ + c1i]), base + o1 + DIM);
        cpasync16(smaddr(&Ks[0][r2i * SQ + c2i]), base + o2 + DIM);
        cpasync16(smaddr(&Vs[0][r0i * SQ + c0i]), base + o0 + 2 * DIM);
        cpasync16(smaddr(&Vs[0][r1i * SQ + c1i]), base + o1 + 2 * DIM);
        cpasync16(smaddr(&Vs[0][r2i * SQ + c2i]), base + o2 + 2 * DIM);
        cpcommit();
    }

    const int ntiles = NTOK / 64;
    for (int kt = 0; kt < ntiles; kt++) {
        const int cur = kt & 1;
        if (kt + 1 < ntiles) {
            const __nv_bfloat16* nb = base + (size_t)(kt + 1) * 64 * QKVC;
            size_t o0 = (size_t)r0i * QKVC + c0i, o1 = (size_t)r1i * QKVC + c1i, o2 = (size_t)r2i * QKVC + c2i;
            cpasync16(smaddr(&Ks[cur ^ 1][r0i * SQ + c0i]), nb + o0 + DIM);
            cpasync16(smaddr(&Ks[cur ^ 1][r1i * SQ + c1i]), nb + o1 + DIM);
            cpasync16(smaddr(&Ks[cur ^ 1][r2i * SQ + c2i]), nb + o2 + DIM);
            cpasync16(smaddr(&Vs[cur ^ 1][r0i * SQ + c0i]), nb + o0 + 2 * DIM);
            cpasync16(smaddr(&Vs[cur ^ 1][r1i * SQ + c1i]), nb + o1 + 2 * DIM);
            cpasync16(smaddr(&Vs[cur ^ 1][r2i * SQ + c2i]), nb + o2 + 2 * DIM);
            cpcommit();
            cpwait1();
        } else {
            cpwait0();
        }
        __syncthreads();

        // S = Q @ K^T (warp: 16 x 64)
        float sacc[8][4];
        #pragma unroll
        for (int ns = 0; ns < 8; ns++)
            #pragma unroll
            for (int q = 0; q < 4; q++) sacc[ns][q] = 0.f;
        #pragma unroll
        for (int kc = 0; kc < 3; kc++) {
            uint32_t aq[4];
            ldsm4(aq, smaddr(&Qs[(wrow0 + lr) * SQ + kc * 16 + lk]));
            #pragma unroll
            for (int p = 0; p < 4; p++) {
                uint32_t bk[4];
                ldsm4(bk, smaddr(&Ks[cur][(p * 16 + lr) * SQ + kc * 16 + lk]));
                mma16(sacc[2 * p],     aq, bk[0], bk[2]);
                mma16(sacc[2 * p + 1], aq, bk[1], bk[3]);
            }
        }
        #pragma unroll
        for (int ns = 0; ns < 8; ns++)
            #pragma unroll
            for (int q = 0; q < 4; q++) sacc[ns][q] *= ATT_SCALE;

        // online softmax on C-fragments
        float rmaxA = -1e30f, rmaxB = -1e30f;
        #pragma unroll
        for (int ns = 0; ns < 8; ns++) {
            rmaxA = fmaxf(rmaxA, fmaxf(sacc[ns][0], sacc[ns][1]));
            rmaxB = fmaxf(rmaxB, fmaxf(sacc[ns][2], sacc[ns][3]));
        }
        rmaxA = fmaxf(rmaxA, __shfl_xor_sync(0xffffffffu, rmaxA, 1));
        rmaxA = fmaxf(rmaxA, __shfl_xor_sync(0xffffffffu, rmaxA, 2));
        rmaxB = fmaxf(rmaxB, __shfl_xor_sync(0xffffffffu, rmaxB, 1));
        rmaxB = fmaxf(rmaxB, __shfl_xor_sync(0xffffffffu, rmaxB, 2));

        float mAn = fmaxf(mA, rmaxA), mBn = fmaxf(mB, rmaxB);
        float fA = __expf(mA - mAn), fB = __expf(mB - mBn);
        mA = mAn; mB = mBn;

        float sumA = 0.f, sumB = 0.f;
        #pragma unroll
        for (int ns = 0; ns < 8; ns++) {
            sacc[ns][0] = __expf(sacc[ns][0] - mA);
            sacc[ns][1] = __expf(sacc[ns][1] - mA);
            sacc[ns][2] = __expf(sacc[ns][2] - mB);
            sacc[ns][3] = __expf(sacc[ns][3] - mB);
            sumA += sacc[ns][0] + sacc[ns][1];
            sumB += sacc[ns][2] + sacc[ns][3];
        }
        sumA += __shfl_xor_sync(0xffffffffu, sumA, 1);
        sumA += __shfl_xor_sync(0xffffffffu, sumA, 2);
        sumB += __shfl_xor_sync(0xffffffffu, sumB, 1);
        sumB += __shfl_xor_sync(0xffffffffu, sumB, 2);
        lA = lA * fA + sumA;
        lB = lB * fB + sumB;

        #pragma unroll
        for (int ns = 0; ns < 6; ns++) {
            oacc[ns][0] *= fA; oacc[ns][1] *= fA;
            oacc[ns][2] *= fB; oacc[ns][3] *= fB;
        }

        // O += P @ V ; P packed from S-fragments, V via ldmatrix.trans
        #pragma unroll
        for (int kc = 0; kc < 4; kc++) {
            uint32_t ap[4];
            ap[0] = packbf(sacc[2 * kc][0],     sacc[2 * kc][1]);
            ap[1] = packbf(sacc[2 * kc][2],     sacc[2 * kc][3]);
            ap[2] = packbf(sacc[2 * kc + 1][0], sacc[2 * kc + 1][1]);
            ap[3] = packbf(sacc[2 * kc + 1][2], sacc[2 * kc + 1][3]);
            #pragma unroll
            for (int p = 0; p < 3; p++) {
                uint32_t bv[4];
                ldsm4t(bv, smaddr(&Vs[cur][(kc * 16 + lr) * SQ + p * 16 + lk]));
                mma16(oacc[2 * p],     ap, bv[0], bv[1]);
                mma16(oacc[2 * p + 1], ap, bv[2], bv[3]);
            }
        }
        __syncthreads();
    }

    float invA = 1.f / lA, invB = 1.f / lB;
    size_t rowA = (size_t)bb * NTOK + q0 + wrow0 + g;
    #pragma unroll
    for (int ns = 0; ns < 6; ns++) {
        int col = hh * HDIM + ns * 8 + tg * 2;
        *(__nv_bfloat162*)&attn[rowA * DIM + col] =
            __floats2bfloat162_rn(oacc[ns][0] * invA, oacc[ns][1] * invA);
        *(__nv_bfloat162*)&attn[(rowA + 8) * DIM + col] =
            __floats2bfloat162_rn(oacc[ns][2] * invB, oacc[ns][3] * invB);
    }
}

// --------------------------- kernel 4: LN ---------------------------------
__global__ void k_ln(const float* __restrict__ in, const float* __restrict__ g,
                     const float* __restrict__ b, __nv_bfloat16* __restrict__ out)
{
    const int row = blockIdx.x;
    const float* p = in + (size_t)row * DIM;
    const int t = threadIdx.x;
    float v0 = p[t], v1 = p[t + 128], v2 = p[t + 256];
    float s = v0 + v1 + v2;

    __shared__ float red[4];
    #pragma unroll
    for (int o = 16; o; o >>= 1) s += __shfl_xor_sync(0xffffffffu, s, o);
    if ((t & 31) == 0) red[t >> 5] = s;
    __syncthreads();
    float mu = (red[0] + red[1] + red[2] + red[3]) * (1.f / DIM);

    float d0 = v0 - mu, d1 = v1 - mu, d2 = v2 - mu;
    float q = d0 * d0 + d1 * d1 + d2 * d2;
    __syncthreads();
    #pragma unroll
    for (int o = 16; o; o >>= 1) q += __shfl_xor_sync(0xffffffffu, q, o);
    if ((t & 31) == 0) red[t >> 5] = q;
    __syncthreads();
    float rstd = rsqrtf((red[0] + red[1] + red[2] + red[3]) * (1.f / DIM) + 1e-6f);

    __nv_bfloat16* po = out + (size_t)row * DIM;
    po[t]       = __float2bfloat16(d0 * rstd * g[t]       + b[t]);
    po[t + 128] = __float2bfloat16(d1 * rstd * g[t + 128] + b[t + 128]);
    po[t + 256] = __float2bfloat16(d2 * rstd * g[t + 256] + b[t + 256]);
}

// ---------------------- kernel 5: transpose back ---------------------------
__global__ void k_transpose_out(const float* __restrict__ h, float* __restrict__ out)
{
    __shared__ float tile[TT][DIM + 1];
    const int tilesPerBatch = NTOK / TT;
    const int bb = blockIdx.x / tilesPerBatch;
    const int n0 = (blockIdx.x % tilesPerBatch) * TT;

    for (int idx = threadIdx.x; idx < DIM * TT; idx += blockDim.x) {
        int t = idx / DIM, c = idx % DIM;
        tile[t][c] = h[((size_t)bb * NTOK + n0 + t) * DIM + c];
    }
    __syncthreads();
    float* ob = out + (size_t)bb * DIM * NTOK;
    for (int idx = threadIdx.x; idx < DIM * TT; idx += blockDim.x) {
        int c = idx / TT, t = idx % TT;
        ob[(size_t)c * NTOK + n0 + t] = tile[t][c];
    }
}

// ------------------------------- launch ------------------------------------
extern "C" void kernel_launch(void* const* d_in, const int* in_sizes, int n_in,
                              void* d_out, int out_size)
{
    const float* x    = (const float*)d_in[0];
    const float* g1   = (const float*)d_in[1];
    const float* b1   = (const float*)d_in[2];
    const float* Wqkv = (const float*)d_in[3];
    const float* Wo   = (const float*)d_in[4];
    const float* bo   = (const float*)d_in[5];
    const float* g2   = (const float*)d_in[6];
    const float* b2   = (const float*)d_in[7];
    const float* W1   = (const float*)d_in[8];
    const float* b1m  = (const float*)d_in[9];
    const float* W2   = (const float*)d_in[10];
    const float* b2m  = (const float*)d_in[11];
    float* out = (float*)d_out;

    float* h;
    __nv_bfloat16 *hnb, *qkvb, *attb, *mlpb, *wqkv, *wo, *w1, *w2;
    cudaGetSymbolAddress((void**)&h,    g_h);
    cudaGetSymbolAddress((void**)&hnb,  g_hnb);
    cudaGetSymbolAddress((void**)&qkvb, g_qkvb);
    cudaGetSymbolAddress((void**)&attb, g_attb);
    cudaGetSymbolAddress((void**)&mlpb, g_mlpb);
    cudaGetSymbolAddress((void**)&wqkv, g_wqkv);
    cudaGetSymbolAddress((void**)&wo,   g_wo);
    cudaGetSymbolAddress((void**)&w1,   g_w1);
    cudaGetSymbolAddress((void**)&w2,   g_w2);

    // weight prep (one launch, all 4 weights)
    k_wprep_all<<<1728, dim3(32, 8)>>>(Wqkv, Wo, W1, W2, wqkv, wo, w1, w2);

    // 1. transpose + LN1
    k_transpose_ln<<<MTOT / TT, 256>>>(x, g1, b1, h, hnb);
    // 2. qkv = hn @ Wqkv
    k_gemm<128, false, false, false, true><<<dim3(QKVC / 64, MTOT / 128), 256>>>(
        hnb, wqkv, nullptr, nullptr, qkvb, MTOT, QKVC, DIM);
    // 3. attention
    k_attn<<<dim3(NTOK / 64, BATCH * NHEADS), 128>>>(qkvb, attb);
    // 4. h += att @ Wo + bo
    k_gemm<64, true, false, true, false><<<dim3(DIM / 64, MTOT / 64), 256>>>(
        attb, wo, bo, h, h, MTOT, DIM, DIM);
    // 5. LN2
    k_ln<<<MTOT, 128>>>(h, g2, b2, hnb);
    // 6. mlp = gelu(hn @ W1 + b1m)
    k_gemm<128, true, true, false, true><<<dim3(MLPH / 64, MTOT / 128), 256>>>(
        hnb, w1, b1m, nullptr, mlpb, MTOT, MLPH, DIM);
    // 7. h += mlp @ W2 + b2m
    k_gemm<64, true, false, true, false><<<dim3(DIM / 64, MTOT / 64), 256>>>(
        mlpb, w2, b2m, h, h, MTOT, DIM, MLPH);
    // 8. transpose back
    k_transpose_out<<<MTOT / TT, 256>>>(h, out);
}

// round 5
// speedup vs baseline: 9.3146x; 1.0107x over previous
#include <cuda_runtime.h>
#include <cuda_bf16.h>
#include <cstdint>
#include <math.h>

// ---------------------------------------------------------------------------
// TransformerBlock: B=2, C=384, N=2048 tokens/batch, H=8 heads, d=48
// fp32 I/O + residual stream, bf16 mma.m16n8k16 + ldmatrix + cp.async.
// Attention: split-KV x2 + exp2 online softmax.
// ---------------------------------------------------------------------------

#define BATCH   2
#define DIM     384
#define NTOK    2048
#define MTOT    (BATCH * NTOK)  // 4096
#define NHEADS  8
#define BH      (BATCH * NHEADS)  // 16
#define HDIM    48
#define QKVC    (3 * DIM)       // 1152
#define MLPH    1536
#define ATT_SCALE 0.14433756729740643f
#define ATT_C   (0.14433756729740643f * 1.4426950408889634f)   // scale * log2(e)
#define SPLIT   2
#define TILES_PER_SPLIT (NTOK / 64 / SPLIT)   // 16

// ----------------------------- scratch ------------------------------------
__device__ float         g_h   [MTOT * DIM];
__device__ __nv_bfloat16 g_hnb [MTOT * DIM];
__device__ __nv_bfloat16 g_qkvb[MTOT * QKVC];
__device__ __nv_bfloat16 g_attb[MTOT * DIM];
__device__ __nv_bfloat16 g_mlpb[MTOT * MLPH];
__device__ __nv_bfloat16 g_wqkv[QKVC * DIM];   // transposed [N][K]
__device__ __nv_bfloat16 g_wo  [DIM * DIM];
__device__ __nv_bfloat16 g_w1  [MLPH * DIM];
__device__ __nv_bfloat16 g_w2  [DIM * MLPH];
// split-KV partials
__device__ float g_po[SPLIT * BH * NTOK * HDIM];   // unnormalized O
__device__ float g_pm[SPLIT * BH * NTOK];          // raw-row-max
__device__ float g_pl[SPLIT * BH * NTOK];          // sum

// --------------------------- asm helpers -----------------------------------
__device__ __forceinline__ void mma16(float* c, const uint32_t* a,
                                      uint32_t b0, uint32_t b1) {
    asm volatile(
        "mma.sync.aligned.m16n8k16.row.col.f32.bf16.bf16.f32 "
        "{%0,%1,%2,%3}, {%4,%5,%6,%7}, {%8,%9}, {%0,%1,%2,%3};\n"
        : "+f"(c[0]), "+f"(c[1]), "+f"(c[2]), "+f"(c[3])
        : "r"(a[0]), "r"(a[1]), "r"(a[2]), "r"(a[3]), "r"(b0), "r"(b1));
}
__device__ __forceinline__ uint32_t packbf(float x, float y) {
    __nv_bfloat162 h = __floats2bfloat162_rn(x, y);
    return *(uint32_t*)&h;
}
__device__ __forceinline__ uint32_t smaddr(const void* p) {
    return (uint32_t)__cvta_generic_to_shared(p);
}
__device__ __forceinline__ void ldsm4(uint32_t* r, uint32_t a) {
    asm volatile("ldmatrix.sync.aligned.m8n8.x4.shared.b16 {%0,%1,%2,%3}, [%4];"
                 : "=r"(r[0]), "=r"(r[1]), "=r"(r[2]), "=r"(r[3]) : "r"(a));
}
__device__ __forceinline__ void ldsm4t(uint32_t* r, uint32_t a) {
    asm volatile("ldmatrix.sync.aligned.m8n8.x4.trans.shared.b16 {%0,%1,%2,%3}, [%4];"
                 : "=r"(r[0]), "=r"(r[1]), "=r"(r[2]), "=r"(r[3]) : "r"(a));
}
__device__ __forceinline__ void cpasync16(uint32_t dst, const void* src) {
    asm volatile("cp.async.ca.shared.global [%0], [%1], 16;\n" :: "r"(dst), "l"(src));
}
__device__ __forceinline__ void cpcommit() { asm volatile("cp.async.commit_group;\n"); }
__device__ __forceinline__ void cpwait1()  { asm volatile("cp.async.wait_group 1;\n"); }
__device__ __forceinline__ void cpwait0()  { asm volatile("cp.async.wait_group 0;\n"); }

// ------------------ fused weight prep: fp32 [R][C] -> bf16 [C][R] ----------
__global__ void k_wprep_all(const float* __restrict__ Wqkv, const float* __restrict__ Wo,
                            const float* __restrict__ W1, const float* __restrict__ W2,
                            __nv_bfloat16* __restrict__ wqkv, __nv_bfloat16* __restrict__ wo,
                            __nv_bfloat16* __restrict__ w1, __nv_bfloat16* __restrict__ w2)
{
    __shared__ float t[32][33];
    int bid = blockIdx.x;
    const float* in; __nv_bfloat16* out; int R, C, rb, cb;
    if (bid < 432)       { int id = bid;        in = Wqkv; out = wqkv; R = 384;  C = 1152; cb = id % 36; rb = id / 36; }
    else if (bid < 576)  { int id = bid - 432;  in = Wo;   out = wo;   R = 384;  C = 384;  cb = id % 12; rb = id / 12; }
    else if (bid < 1152) { int id = bid - 576;  in = W1;   out = w1;   R = 384;  C = 1536; cb = id % 48; rb = id / 48; }
    else                 { int id = bid - 1152; in = W2;   out = w2;   R = 1536; C = 384;  cb = id % 12; rb = id / 12; }

    const int c = cb * 32 + threadIdx.x;
    #pragma unroll
    for (int j = 0; j < 4; j++) {
        int r = rb * 32 + threadIdx.y + j * 8;
        t[threadIdx.y + j * 8][threadIdx.x] = in[(size_t)r * C + c];
    }
    __syncthreads();
    const int r2 = rb * 32 + threadIdx.x;
    #pragma unroll
    for (int j = 0; j < 4; j++) {
        int c2 = cb * 32 + threadIdx.y + j * 8;
        out[(size_t)c2 * R + r2] = __float2bfloat16(t[threadIdx.x][threadIdx.y + j * 8]);
    }
}

// ------------------------ kernel 1: transpose + LN1 ------------------------
#define TT 16
__global__ void k_transpose_ln(const float* __restrict__ x,
                               const float* __restrict__ g,
                               const float* __restrict__ b,
                               float* __restrict__ h,
                               __nv_bfloat16* __restrict__ hn)
{
    __shared__ float tile[TT][DIM + 1];
    const int tilesPerBatch = NTOK / TT;
    const int bb = blockIdx.x / tilesPerBatch;
    const int n0 = (blockIdx.x % tilesPerBatch) * TT;
    const float* xb = x + (size_t)bb * DIM * NTOK;

    for (int idx = threadIdx.x; idx < DIM * TT; idx += blockDim.x) {
        int c = idx / TT, t = idx % TT;
        tile[t][c] = xb[(size_t)c * NTOK + n0 + t];
    }
    __syncthreads();

    const int wid = threadIdx.x >> 5, lane = threadIdx.x & 31;
    for (int t = wid; t < TT; t += (int)(blockDim.x >> 5)) {
        float s = 0.f;
        #pragma unroll
        for (int c = lane; c < DIM; c += 32) s += tile[t][c];
        #pragma unroll
        for (int o = 16; o; o >>= 1) s += __shfl_xor_sync(0xffffffffu, s, o);
        float mu = s * (1.f / DIM);
        float vs = 0.f;
        #pragma unroll
        for (int c = lane; c < DIM; c += 32) { float d = tile[t][c] - mu; vs += d * d; }
        #pragma unroll
        for (int o = 16; o; o >>= 1) vs += __shfl_xor_sync(0xffffffffu, vs, o);
        float rstd = rsqrtf(vs * (1.f / DIM) + 1e-6f);
        size_t row = ((size_t)bb * NTOK + n0 + t) * DIM;
        for (int c = lane; c < DIM; c += 32) {
            float v = tile[t][c];
            h[row + c]  = v;
            hn[row + c] = __float2bfloat16((v - mu) * rstd * g[c] + b[c]);
        }
    }
}

// ----------------- kernel 2: bf16 GEMM (ldmatrix + cp.async) ---------------
template<int BM, bool BIAS, bool GELU_, bool RES, bool OUTBF>
__global__ void __launch_bounds__(256)
k_gemm(const __nv_bfloat16* __restrict__ A, const __nv_bfloat16* __restrict__ Bt,
       const float* __restrict__ bias, const float* __restrict__ res,
       void* __restrict__ Cout, int M, int N, int K)
{
    constexpr int BN = 64, BK = 32;
    constexpr int SA = 40;
    constexpr int MW = BM / 32;
    constexpr int WN = BN / (8 / MW);
    constexpr int NS = WN / 8;
    __shared__ __nv_bfloat16 As[2][BM * SA];
    __shared__ __nv_bfloat16 Bs[2][BN * SA];

    const int tid = threadIdx.x;
    const int m0 = blockIdx.y * BM, n0 = blockIdx.x * BN;
    const int wid = tid >> 5, lane = tid & 31;
    const int g = lane >> 2, tg = lane & 3;
    const int wm0 = (wid % MW) * 32;
    const int wn0 = (wid / MW) * WN;
    const int lr = lane & 15, lk = (lane >> 4) * 8;

    float acc[2][NS][4];
    #pragma unroll
    for (int i = 0; i < 2; i++)
        #pragma unroll
        for (int j = 0; j < NS; j++)
            #pragma unroll
            for (int q = 0; q < 4; q++) acc[i][j][q] = 0.f;

    const int a_r = tid >> 2, a_c = (tid & 3) * 8;
    const __nv_bfloat16* Ap = A  + (size_t)(m0 + a_r) * K + a_c;
    const __nv_bfloat16* Bp = Bt + (size_t)(n0 + a_r) * K + a_c;

    uint32_t sA[2], sA2[2], sB[2];
    #pragma unroll
    for (int bset = 0; bset < 2; bset++) {
        sA[bset]  = smaddr(&As[bset][a_r * SA + a_c]);
        sA2[bset] = smaddr(&As[bset][(a_r + 64) * SA + a_c]);
        sB[bset]  = smaddr(&Bs[bset][a_r * SA + a_c]);
    }

    const int ntiles = K / BK;
    cpasync16(sA[0], Ap);
    if (BM == 128) cpasync16(sA2[0], Ap + (size_t)64 * K);
    cpasync16(sB[0], Bp);
    cpcommit();

    for (int t = 0; t < ntiles; t++) {
        const int cur = t & 1;
        if (t + 1 < ntiles) {
            const __nv_bfloat16* an = Ap + (t + 1) * BK;
            const __nv_bfloat16* bn = Bp + (t + 1) * BK;
            cpasync16(sA[cur ^ 1], an);
            if (BM == 128) cpasync16(sA2[cur ^ 1], an + (size_t)64 * K);
            cpasync16(sB[cur ^ 1], bn);
            cpcommit();
            cpwait1();
        } else {
            cpwait0();
        }
        __syncthreads();

        #pragma unroll
        for (int kk = 0; kk < 2; kk++) {
            uint32_t af[2][4];
            #pragma unroll
            for (int ms = 0; ms < 2; ms++)
                ldsm4(af[ms], smaddr(&As[cur][(wm0 + ms * 16 + lr) * SA + kk * 16 + lk]));
            #pragma unroll
            for (int p = 0; p < NS / 2; p++) {
                uint32_t bf[4];
                ldsm4(bf, smaddr(&Bs[cur][(wn0 + p * 16 + lr) * SA + kk * 16 + lk]));
                #pragma unroll
                for (int ms = 0; ms < 2; ms++) {
                    mma16(acc[ms][2 * p],     af[ms], bf[0], bf[2]);
                    mma16(acc[ms][2 * p + 1], af[ms], bf[1], bf[3]);
                }
            }
        }
        __syncthreads();
    }

    #pragma unroll
    for (int ms = 0; ms < 2; ms++) {
        #pragma unroll
        for (int rr = 0; rr < 2; rr++) {
            size_t m = (size_t)m0 + wm0 + ms * 16 + g + rr * 8;
            #pragma unroll
            for (int ns = 0; ns < NS; ns++) {
                int n = n0 + wn0 + ns * 8 + tg * 2;
                float v0 = acc[ms][ns][rr * 2 + 0];
                float v1 = acc[ms][ns][rr * 2 + 1];
                if (BIAS) { v0 += bias[n]; v1 += bias[n + 1]; }
                if (GELU_) {
                    v0 = 0.5f * v0 * (1.f + erff(v0 * 0.70710678118654752f));
                    v1 = 0.5f * v1 * (1.f + erff(v1 * 0.70710678118654752f));
                }
                if (RES) {
                    v0 += res[m * N + n];
                    v1 += res[m * N + n + 1];
                }
                if (OUTBF) {
                    *(__nv_bfloat162*)((__nv_bfloat16*)Cout + m * N + n) =
                        __floats2bfloat162_rn(v0, v1);
                } else {
                    *(float2*)((float*)Cout + m * N + n) = make_float2(v0, v1);
                }
            }
        }
    }
}

// ---------------- kernel 3: split-KV bf16 flash attention ------------------
// grid (NTOK/64, BH, SPLIT). BQ=64 (4 warps), per-split KV = 1024 tokens.
// Writes unnormalized partial O (fp32) + raw-max m + sum l.
__global__ void __launch_bounds__(128)
k_attn(const __nv_bfloat16* __restrict__ qkv,
       float* __restrict__ po, float* __restrict__ pm, float* __restrict__ pl)
{
    constexpr int SQ = 56;
    __shared__ __nv_bfloat16 Qs[64 * SQ];
    __shared__ __nv_bfloat16 Ks[2][64 * SQ];
    __shared__ __nv_bfloat16 Vs[2][64 * SQ];

    const int bh = blockIdx.y;
    const int sp = blockIdx.z;
    const int bb = bh >> 3, hh = bh & 7;
    const __nv_bfloat16* base = qkv + (size_t)bb * NTOK * QKVC + hh * HDIM;
    const __nv_bfloat16* kvbase = base + (size_t)sp * TILES_PER_SPLIT * 64 * QKVC;
    const int q0 = blockIdx.x * 64;
    const int tid = threadIdx.x;
    const int w = tid >> 5, lane = tid & 31;
    const int g = lane >> 2, tg = lane & 3;
    const int wrow0 = w * 16;
    const int lr = lane & 15, lk = (lane >> 4) * 8;

    #pragma unroll
    for (int j = 0; j < 3; j++) {
        int idx = tid + j * 128;
        int r = idx / 6, c8 = (idx % 6) * 8;
        *(uint4*)&Qs[r * SQ + c8] = *(const uint4*)(base + (size_t)(q0 + r) * QKVC + c8);
    }

    float oacc[6][4];
    #pragma unroll
    for (int i = 0; i < 6; i++)
        #pragma unroll
        for (int j = 0; j < 4; j++) oacc[i][j] = 0.f;
    float mA = -1e30f, mB = -1e30f, lA = 0.f, lB = 0.f;

    const int r0i = (tid) / 6, c0i = ((tid) % 6) * 8;
    const int r1i = (tid + 128) / 6, c1i = ((tid + 128) % 6) * 8;
    const int r2i = (tid + 256) / 6, c2i = ((tid + 256) % 6) * 8;
    const size_t o0 = (size_t)r0i * QKVC + c0i;
    const size_t o1 = (size_t)r1i * QKVC + c1i;
    const size_t o2 = (size_t)r2i * QKVC + c2i;

    // prologue: tile 0 of this split
    cpasync16(smaddr(&Ks[0][r0i * SQ + c0i]), kvbase + o0 + DIM);
    cpasync16(smaddr(&Ks[0][r1i * SQ + c1i]), kvbase + o1 + DIM);
    cpasync16(smaddr(&Ks[0][r2i * SQ + c2i]), kvbase + o2 + DIM);
    cpasync16(smaddr(&Vs[0][r0i * SQ + c0i]), kvbase + o0 + 2 * DIM);
    cpasync16(smaddr(&Vs[0][r1i * SQ + c1i]), kvbase + o1 + 2 * DIM);
    cpasync16(smaddr(&Vs[0][r2i * SQ + c2i]), kvbase + o2 + 2 * DIM);
    cpcommit();

    for (int kt = 0; kt < TILES_PER_SPLIT; kt++) {
        const int cur = kt & 1;
        if (kt + 1 < TILES_PER_SPLIT) {
            const __nv_bfloat16* nb = kvbase + (size_t)(kt + 1) * 64 * QKVC;
            cpasync16(smaddr(&Ks[cur ^ 1][r0i * SQ + c0i]), nb + o0 + DIM);
            cpasync16(smaddr(&Ks[cur ^ 1][r1i * SQ + c1i]), nb + o1 + DIM);
            cpasync16(smaddr(&Ks[cur ^ 1][r2i * SQ + c2i]), nb + o2 + DIM);
            cpasync16(smaddr(&Vs[cur ^ 1][r0i * SQ + c0i]), nb + o0 + 2 * DIM);
            cpasync16(smaddr(&Vs[cur ^ 1][r1i * SQ + c1i]), nb + o1 + 2 * DIM);
            cpasync16(smaddr(&Vs[cur ^ 1][r2i * SQ + c2i]), nb + o2 + 2 * DIM);
            cpcommit();
            cpwait1();
        } else {
            cpwait0();
        }
        __syncthreads();

        // S = Q @ K^T (warp: 16 x 64), raw units
        float sacc[8][4];
        #pragma unroll
        for (int ns = 0; ns < 8; ns++)
            #pragma unroll
            for (int q = 0; q < 4; q++) sacc[ns][q] = 0.f;
        #pragma unroll
        for (int kc = 0; kc < 3; kc++) {
            uint32_t aq[4];
            ldsm4(aq, smaddr(&Qs[(wrow0 + lr) * SQ + kc * 16 + lk]));
            #pragma unroll
            for (int p = 0; p < 4; p++) {
                uint32_t bk[4];
                ldsm4(bk, smaddr(&Ks[cur][(p * 16 + lr) * SQ + kc * 16 + lk]));
                mma16(sacc[2 * p],     aq, bk[0], bk[2]);
                mma16(sacc[2 * p + 1], aq, bk[1], bk[3]);
            }
        }

        // online softmax (raw max, exp2 with folded scale)
        float rmaxA = -1e30f, rmaxB = -1e30f;
        #pragma unroll
        for (int ns = 0; ns < 8; ns++) {
            rmaxA = fmaxf(rmaxA, fmaxf(sacc[ns][0], sacc[ns][1]));
            rmaxB = fmaxf(rmaxB, fmaxf(sacc[ns][2], sacc[ns][3]));
        }
        rmaxA = fmaxf(rmaxA, __shfl_xor_sync(0xffffffffu, rmaxA, 1));
        rmaxA = fmaxf(rmaxA, __shfl_xor_sync(0xffffffffu, rmaxA, 2));
        rmaxB = fmaxf(rmaxB, __shfl_xor_sync(0xffffffffu, rmaxB, 1));
        rmaxB = fmaxf(rmaxB, __shfl_xor_sync(0xffffffffu, rmaxB, 2));

        float mAn = fmaxf(mA, rmaxA), mBn = fmaxf(mB, rmaxB);
        float fA = exp2f((mA - mAn) * ATT_C), fB = exp2f((mB - mBn) * ATT_C);
        mA = mAn; mB = mBn;
        const float nmcA = -mA * ATT_C, nmcB = -mB * ATT_C;

        float sumA = 0.f, sumB = 0.f;
        #pragma unroll
        for (int ns = 0; ns < 8; ns++) {
            sacc[ns][0] = exp2f(fmaf(sacc[ns][0], ATT_C, nmcA));
            sacc[ns][1] = exp2f(fmaf(sacc[ns][1], ATT_C, nmcA));
            sacc[ns][2] = exp2f(fmaf(sacc[ns][2], ATT_C, nmcB));
            sacc[ns][3] = exp2f(fmaf(sacc[ns][3], ATT_C, nmcB));
            sumA += sacc[ns][0] + sacc[ns][1];
            sumB += sacc[ns][2] + sacc[ns][3];
        }
        sumA += __shfl_xor_sync(0xffffffffu, sumA, 1);
        sumA += __shfl_xor_sync(0xffffffffu, sumA, 2);
        sumB += __shfl_xor_sync(0xffffffffu, sumB, 1);
        sumB += __shfl_xor_sync(0xffffffffu, sumB, 2);
        lA = lA * fA + sumA;
        lB = lB * fB + sumB;

        #pragma unroll
        for (int ns = 0; ns < 6; ns++) {
            oacc[ns][0] *= fA; oacc[ns][1] *= fA;
            oacc[ns][2] *= fB; oacc[ns][3] *= fB;
        }

        // O += P @ V
        #pragma unroll
        for (int kc = 0; kc < 4; kc++) {
            uint32_t ap[4];
            ap[0] = packbf(sacc[2 * kc][0],     sacc[2 * kc][1]);
            ap[1] = packbf(sacc[2 * kc][2],     sacc[2 * kc][3]);
            ap[2] = packbf(sacc[2 * kc + 1][0], sacc[2 * kc + 1][1]);
            ap[3] = packbf(sacc[2 * kc + 1][2], sacc[2 * kc + 1][3]);
            #pragma unroll
            for (int p = 0; p < 3; p++) {
                uint32_t bv[4];
                ldsm4t(bv, smaddr(&Vs[cur][(kc * 16 + lr) * SQ + p * 16 + lk]));
                mma16(oacc[2 * p],     ap, bv[0], bv[1]);
                mma16(oacc[2 * p + 1], ap, bv[2], bv[3]);
            }
        }
        __syncthreads();
    }

    // write partials (unnormalized O, raw m, l)
    const size_t prowA = ((size_t)(sp * BH + bh) * NTOK) + q0 + wrow0 + g;
    #pragma unroll
    for (int ns = 0; ns < 6; ns++) {
        int col = ns * 8 + tg * 2;
        *(float2*)&po[prowA * HDIM + col] = make_float2(oacc[ns][0], oacc[ns][1]);
        *(float2*)&po[(prowA + 8) * HDIM + col] = make_float2(oacc[ns][2], oacc[ns][3]);
    }
    if (tg == 0) {
        pm[prowA] = mA; pl[prowA] = lA;
        pm[prowA + 8] = mB; pl[prowA + 8] = lB;
    }
}

// ---------------- kernel 3b: split-KV merge -------------------------------
__global__ void k_attn_merge(const float* __restrict__ po, const float* __restrict__ pm,
                             const float* __restrict__ pl, __nv_bfloat16* __restrict__ attn)
{
    const int e = blockIdx.x * 256 + threadIdx.x;   // < BH*NTOK*HDIM
    if (e >= BH * NTOK * HDIM) return;
    const int d = e % HDIM;
    const int row = e / HDIM;                        // bh*NTOK + q
    const float m0 = pm[row], m1 = pm[BH * NTOK + row];
    const float l0 = pl[row], l1 = pl[BH * NTOK + row];
    const float m = fmaxf(m0, m1);
    const float w0 = exp2f((m0 - m) * ATT_C);
    const float w1 = exp2f((m1 - m) * ATT_C);
    const float o0 = po[(size_t)row * HDIM + d];
    const float o1 = po[(size_t)(BH * NTOK + row) * HDIM + d];
    const float o = (o0 * w0 + o1 * w1) / (l0 * w0 + l1 * w1);
    const int bh = row >> 11, q = row & (NTOK - 1);
    const int bb = bh >> 3, hh = bh & 7;
    attn[((size_t)(bb * NTOK + q)) * DIM + hh * HDIM + d] = __float2bfloat16(o);
}

// --------------------------- kernel 4: LN ---------------------------------
__global__ void k_ln(const float* __restrict__ in, const float* __restrict__ g,
                     const float* __restrict__ b, __nv_bfloat16* __restrict__ out)
{
    const int row = blockIdx.x;
    const float* p = in + (size_t)row * DIM;
    const int t = threadIdx.x;
    float v0 = p[t], v1 = p[t + 128], v2 = p[t + 256];
    float s = v0 + v1 + v2;

    __shared__ float red[4];
    #pragma unroll
    for (int o = 16; o; o >>= 1) s += __shfl_xor_sync(0xffffffffu, s, o);
    if ((t & 31) == 0) red[t >> 5] = s;
    __syncthreads();
    float mu = (red[0] + red[1] + red[2] + red[3]) * (1.f / DIM);

    float d0 = v0 - mu, d1 = v1 - mu, d2 = v2 - mu;
    float q = d0 * d0 + d1 * d1 + d2 * d2;
    __syncthreads();
    #pragma unroll
    for (int o = 16; o; o >>= 1) q += __shfl_xor_sync(0xffffffffu, q, o);
    if ((t & 31) == 0) red[t >> 5] = q;
    __syncthreads();
    float rstd = rsqrtf((red[0] + red[1] + red[2] + red[3]) * (1.f / DIM) + 1e-6f);

    __nv_bfloat16* po = out + (size_t)row * DIM;
    po[t]       = __float2bfloat16(d0 * rstd * g[t]       + b[t]);
    po[t + 128] = __float2bfloat16(d1 * rstd * g[t + 128] + b[t + 128]);
    po[t + 256] = __float2bfloat16(d2 * rstd * g[t + 256] + b[t + 256]);
}

// ---------------------- kernel 5: transpose back ---------------------------
__global__ void k_transpose_out(const float* __restrict__ h, float* __restrict__ out)
{
    __shared__ float tile[TT][DIM + 1];
    const int tilesPerBatch = NTOK / TT;
    const int bb = blockIdx.x / tilesPerBatch;
    const int n0 = (blockIdx.x % tilesPerBatch) * TT;

    for (int idx = threadIdx.x; idx < DIM * TT; idx += blockDim.x) {
        int t = idx / DIM, c = idx % DIM;
        tile[t][c] = h[((size_t)bb * NTOK + n0 + t) * DIM + c];
    }
    __syncthreads();
    float* ob = out + (size_t)bb * DIM * NTOK;
    for (int idx = threadIdx.x; idx < DIM * TT; idx += blockDim.x) {
        int c = idx / TT, t = idx % TT;
        ob[(size_t)c * NTOK + n0 + t] = tile[t][c];
    }
}

// ------------------------------- launch ------------------------------------
extern "C" void kernel_launch(void* const* d_in, const int* in_sizes, int n_in,
                              void* d_out, int out_size)
{
    const float* x    = (const float*)d_in[0];
    const float* g1   = (const float*)d_in[1];
    const float* b1   = (const float*)d_in[2];
    const float* Wqkv = (const float*)d_in[3];
    const float* Wo   = (const float*)d_in[4];
    const float* bo   = (const float*)d_in[5];
    const float* g2   = (const float*)d_in[6];
    const float* b2   = (const float*)d_in[7];
    const float* W1   = (const float*)d_in[8];
    const float* b1m  = (const float*)d_in[9];
    const float* W2   = (const float*)d_in[10];
    const float* b2m  = (const float*)d_in[11];
    float* out = (float*)d_out;

    float *h, *po, *pm, *pl;
    __nv_bfloat16 *hnb, *qkvb, *attb, *mlpb, *wqkv, *wo, *w1, *w2;
    cudaGetSymbolAddress((void**)&h,    g_h);
    cudaGetSymbolAddress((void**)&hnb,  g_hnb);
    cudaGetSymbolAddress((void**)&qkvb, g_qkvb);
    cudaGetSymbolAddress((void**)&attb, g_attb);
    cudaGetSymbolAddress((void**)&mlpb, g_mlpb);
    cudaGetSymbolAddress((void**)&wqkv, g_wqkv);
    cudaGetSymbolAddress((void**)&wo,   g_wo);
    cudaGetSymbolAddress((void**)&w1,   g_w1);
    cudaGetSymbolAddress((void**)&w2,   g_w2);
    cudaGetSymbolAddress((void**)&po,   g_po);
    cudaGetSymbolAddress((void**)&pm,   g_pm);
    cudaGetSymbolAddress((void**)&pl,   g_pl);

    k_wprep_all<<<1728, dim3(32, 8)>>>(Wqkv, Wo, W1, W2, wqkv, wo, w1, w2);

    // 1. transpose + LN1
    k_transpose_ln<<<MTOT / TT, 256>>>(x, g1, b1, h, hnb);
    // 2. qkv = hn @ Wqkv
    k_gemm<128, false, false, false, true><<<dim3(QKVC / 64, MTOT / 128), 256>>>(
        hnb, wqkv, nullptr, nullptr, qkvb, MTOT, QKVC, DIM);
    // 3. attention (split-KV) + merge
    k_attn<<<dim3(NTOK / 64, BH, SPLIT), 128>>>(qkvb, po, pm, pl);
    k_attn_merge<<<(BH * NTOK * HDIM + 255) / 256, 256>>>(po, pm, pl, attb);
    // 4. h += att @ Wo + bo
    k_gemm<64, true, false, true, false><<<dim3(DIM / 64, MTOT / 64), 256>>>(
        attb, wo, bo, h, h, MTOT, DIM, DIM);
    // 5. LN2
    k_ln<<<MTOT, 128>>>(h, g2, b2, hnb);
    // 6. mlp = gelu(hn @ W1 + b1m)
    k_gemm<128, true, true, false, true><<<dim3(MLPH / 64, MTOT / 128), 256>>>(
        hnb, w1, b1m, nullptr, mlpb, MTOT, MLPH, DIM);
    // 7. h += mlp @ W2 + b2m
    k_gemm<64, true, false, true, false><<<dim3(DIM / 64, MTOT / 64), 256>>>(
        mlpb, w2, b2m, h, h, MTOT, DIM, MLPH);
    // 8. transpose back
    k_transpose_out<<<MTOT / TT, 256>>>(h, out);
}